// round 11
// baseline (speedup 1.0000x reference)
#include <cuda_runtime.h>
#include <cuda_bf16.h>
#include <cuda_fp16.h>
#include <math.h>

#define D 128
#define H 4
#define DK 32
#define BATCH 16
#define SEQ 2048
#define ROWS (BATCH*SEQ)   // 32768
#define LNEPS 1e-5f

// ---------------- scratch (static device globals; no allocs allowed) ----------
__device__ float g_xn[ROWS*D];
__device__ float g_sa[ROWS*D];
__device__ float g_h [ROWS*D];
__device__ float g_wr[5*D*D];             // tf32-rounded weights (q,k,v,w1,w2)
__device__ int   g_cnt[BATCH];
__device__ int   g_idx[BATCH*SEQ];
__device__ __half g_qh[ROWS*D];           // fp16 Q (relu'd)
__device__ __half g_kh[ROWS*D];           // fp16 K
__device__ __half g_vh[ROWS*D];           // fp16 V

// ---------------- helpers ------------------------------------------------------
__device__ __forceinline__ unsigned tf32r(float x) {
    unsigned u;
    asm("cvt.rna.tf32.f32 %0, %1;" : "=r"(u) : "f"(x));
    return u;
}
__device__ __forceinline__ unsigned packh(float a, float b) {
    __half2 t = __floats2half2_rn(a, b);
    return *(unsigned*)&t;
}
__device__ __forceinline__ unsigned h2exp2(float a, float b) {
    unsigned u = packh(a, b), r;
    asm("ex2.approx.f16x2 %0, %1;" : "=r"(r) : "r"(u));
    return r;
}

#define MMA_TF32(c, a, b0, b1) \
    asm volatile("mma.sync.aligned.m16n8k8.row.col.f32.tf32.tf32.f32 " \
        "{%0,%1,%2,%3}, {%4,%5,%6,%7}, {%8,%9}, {%0,%1,%2,%3};" \
        : "+f"(c[0]), "+f"(c[1]), "+f"(c[2]), "+f"(c[3]) \
        : "r"(a[0]), "r"(a[1]), "r"(a[2]), "r"(a[3]), "r"(b0), "r"(b1))

#define MMA_F16(c, a, b0, b1) \
    asm volatile("mma.sync.aligned.m16n8k16.row.col.f32.f16.f16.f32 " \
        "{%0,%1,%2,%3}, {%4,%5,%6,%7}, {%8,%9}, {%0,%1,%2,%3};" \
        : "+f"(c[0]), "+f"(c[1]), "+f"(c[2]), "+f"(c[3]) \
        : "r"(a[0]), "r"(a[1]), "r"(a[2]), "r"(a[3]), "r"(b0), "r"(b1))

#define LDSM_X4(r, addr) \
    asm volatile("ldmatrix.sync.aligned.m8n8.x4.shared.b16 {%0,%1,%2,%3}, [%4];" \
        : "=r"(r[0]), "=r"(r[1]), "=r"(r[2]), "=r"(r[3]) : "r"(addr))

#define LDSM_X4_T(r, addr) \
    asm volatile("ldmatrix.sync.aligned.m8n8.x4.trans.shared.b16 {%0,%1,%2,%3}, [%4];" \
        : "=r"(r[0]), "=r"(r[1]), "=r"(r[2]), "=r"(r[3]) : "r"(addr))

#define CPA16(dst, src, pbytes) \
    asm volatile("cp.async.cg.shared.global [%0], [%1], 16, %2;" \
        :: "r"(dst), "l"(src), "r"(pbytes))
#define CPC() asm volatile("cp.async.commit_group;" ::: "memory")
#define CPW0() asm volatile("cp.async.wait_group 0;" ::: "memory")
#define CPW1() asm volatile("cp.async.wait_group 1;" ::: "memory")

__device__ __forceinline__ unsigned s2u(const void* p) {
    return (unsigned)__cvta_generic_to_shared(p);
}

// ---------------- LayerNorm: half-warp per row; optional tf32-rounded output ---
template<bool RND>
__global__ void ln_kernel(const float* __restrict__ in, const float* __restrict__ add,
                          float* __restrict__ sum_out, float* __restrict__ ln_out,
                          const float* __restrict__ w, const float* __restrict__ b) {
    int row = blockIdx.x * 16 + (threadIdx.x >> 4);
    int l   = threadIdx.x & 15;
    const float4* ip = (const float4*)(in + (size_t)row * D);
    float4 v0 = ip[l*2], v1 = ip[l*2+1];
    if (add != nullptr) {
        const float4* ap = (const float4*)(add + (size_t)row * D);
        float4 a0 = ap[l*2], a1 = ap[l*2+1];
        v0.x += a0.x; v0.y += a0.y; v0.z += a0.z; v0.w += a0.w;
        v1.x += a1.x; v1.y += a1.y; v1.z += a1.z; v1.w += a1.w;
        float4* sp = (float4*)(sum_out + (size_t)row * D);
        sp[l*2] = v0; sp[l*2+1] = v1;
    }
    float s = v0.x+v0.y+v0.z+v0.w + v1.x+v1.y+v1.z+v1.w;
    #pragma unroll
    for (int o = 8; o; o >>= 1) s += __shfl_xor_sync(0xffffffffu, s, o);
    float mu = s * (1.0f / D);
    float d0x=v0.x-mu, d0y=v0.y-mu, d0z=v0.z-mu, d0w=v0.w-mu;
    float d1x=v1.x-mu, d1y=v1.y-mu, d1z=v1.z-mu, d1w=v1.w-mu;
    float ss = d0x*d0x+d0y*d0y+d0z*d0z+d0w*d0w + d1x*d1x+d1y*d1y+d1z*d1z+d1w*d1w;
    #pragma unroll
    for (int o = 8; o; o >>= 1) ss += __shfl_xor_sync(0xffffffffu, ss, o);
    float rstd = rsqrtf(ss * (1.0f / D) + LNEPS);
    float4 w0 = ((const float4*)w)[l*2], w1 = ((const float4*)w)[l*2+1];
    float4 b0 = ((const float4*)b)[l*2], b1 = ((const float4*)b)[l*2+1];
    float4 o0, o1;
    o0.x = d0x*rstd*w0.x + b0.x; o0.y = d0y*rstd*w0.y + b0.y;
    o0.z = d0z*rstd*w0.z + b0.z; o0.w = d0w*rstd*w0.w + b0.w;
    o1.x = d1x*rstd*w1.x + b1.x; o1.y = d1y*rstd*w1.y + b1.y;
    o1.z = d1z*rstd*w1.z + b1.z; o1.w = d1w*rstd*w1.w + b1.w;
    if (RND) {
        o0.x = __uint_as_float(tf32r(o0.x)); o0.y = __uint_as_float(tf32r(o0.y));
        o0.z = __uint_as_float(tf32r(o0.z)); o0.w = __uint_as_float(tf32r(o0.w));
        o1.x = __uint_as_float(tf32r(o1.x)); o1.y = __uint_as_float(tf32r(o1.y));
        o1.z = __uint_as_float(tf32r(o1.z)); o1.w = __uint_as_float(tf32r(o1.w));
    }
    float4* op = (float4*)(ln_out + (size_t)row * D);
    op[l*2] = o0; op[l*2+1] = o1;
}

// ---------------- prep: mask compaction + tf32-round all weights ---------------
__global__ void prep_kernel(const int* __restrict__ mask,
                            int* __restrict__ idx, int* __restrict__ cnt,
                            const float* __restrict__ wq, const float* __restrict__ wk,
                            const float* __restrict__ wv, const float* __restrict__ w1,
                            const float* __restrict__ w2, float* __restrict__ wr) {
    __shared__ int wsum[32];
    if (blockIdx.x >= 16) {
        int i = (blockIdx.x - 16) * 1024 + threadIdx.x;
        int which = i >> 14, off = i & 16383;
        const float* srcs[5] = {wq, wk, wv, w1, w2};
        wr[i] = __uint_as_float(tf32r(srcs[which][off]));
        return;
    }
    int b = blockIdx.x, t = threadIdx.x;
    const int* mb = mask + b * SEQ;
    int m0 = mb[2*t], m1 = mb[2*t+1];
    int s = m0 + m1;
    int lane = t & 31, w = t >> 5;
    int v = s;
    #pragma unroll
    for (int o = 1; o < 32; o <<= 1) {
        int u = __shfl_up_sync(0xffffffffu, v, o);
        if (lane >= o) v += u;
    }
    if (lane == 31) wsum[w] = v;
    __syncthreads();
    if (t < 32) {
        int u = wsum[t];
        #pragma unroll
        for (int o = 1; o < 32; o <<= 1) {
            int x = __shfl_up_sync(0xffffffffu, u, o);
            if (t >= o) u += x;
        }
        wsum[t] = u;
    }
    __syncthreads();
    int p = v - s + (w ? wsum[w-1] : 0);
    if (m0) idx[b*SEQ + p++] = 2*t;
    if (m1) idx[b*SEQ + p]   = 2*t + 1;
    if (t == 1023) cnt[b] = wsum[31];
}

// ---------------- pipelined tf32 GEMM (QKV): A resident, W streamed, fp16 out --
#define ASTR 132
#define WSTR 36
#define GEMM_SMEM (128*ASTR*4 + 2*128*WSTR*4)   // 104448 B

__global__ __launch_bounds__(256) void qkv_kernel(const float* __restrict__ A,
        const float* __restrict__ W0, const float* __restrict__ W1,
        const float* __restrict__ W2,
        __half* __restrict__ O0, __half* __restrict__ O1, __half* __restrict__ O2) {
    extern __shared__ float sm[];
    float* sA = sm;
    float* sW0 = sm + 128 * ASTR;
    float* sW1 = sW0 + 128 * WSTR;
    int tid = threadIdx.x, warp = tid >> 5, lane = tid & 31;
    int g = lane >> 2, tig = lane & 3;
    int rowBase = blockIdx.x * 128;

    const float* Ws[3] = {W0, W1, W2};
    __half* Os[3] = {O0, O1, O2};

    for (int i = tid; i < 128 * 32; i += 256) {
        int r = i >> 5, c4 = (i & 31) * 4;
        CPA16(s2u(sA + r * ASTR + c4), &A[(size_t)(rowBase + r) * D + c4], 16);
    }
    CPC();
    for (int i = tid; i < 128 * 8; i += 256) {
        int n = i >> 3, seg = (i & 7) * 4;
        CPA16(s2u(sW0 + n * WSTR + seg), &W0[(size_t)n * D + seg], 16);
    }
    CPC();

    unsigned aBase = s2u(sA) +
        (((warp * 16 + (lane & 7) + ((lane >> 3) & 1) * 8) * ASTR + (lane >> 4) * 4) << 2);
    unsigned wOff =
        ((((lane & 7) + (lane >> 4) * 8) * WSTR + ((lane >> 3) & 1) * 4) << 2);
    unsigned wBase[2] = { s2u(sW0) + wOff, s2u(sW1) + wOff };

    float c[16][4] = {};
    int buf = 0;

    #pragma unroll
    for (int t = 0; t < 12; t++) {
        int wi = t >> 2, kc = t & 3;
        __syncthreads();
        if (t + 1 < 12) {
            const float* Wn = Ws[(t + 1) >> 2];
            int kcn = (t + 1) & 3;
            float* dst = buf ? sW0 : sW1;
            for (int i = tid; i < 128 * 8; i += 256) {
                int n = i >> 3, seg = (i & 7) * 4;
                CPA16(s2u(dst + n * WSTR + seg), &Wn[(size_t)n * D + kcn * 32 + seg], 16);
            }
            CPC();
            CPW1();
        } else {
            CPW0();
        }
        __syncthreads();

        #pragma unroll
        for (int k8 = 0; k8 < 4; k8++) {
            unsigned a[4];
            LDSM_X4(a, aBase + kc * 128 + k8 * 32);
            #pragma unroll
            for (int np = 0; np < 8; np++) {
                unsigned bb[4];
                LDSM_X4(bb, wBase[buf] + np * (16 * WSTR * 4) + k8 * 32);
                MMA_TF32(c[np*2],     a, bb[0], bb[1]);
                MMA_TF32(c[np*2 + 1], a, bb[2], bb[3]);
            }
        }

        if (kc == 3) {
            __half* O = Os[wi];
            int row0 = rowBase + warp * 16 + g;
            bool relu = (wi == 0);
            #pragma unroll
            for (int nt = 0; nt < 16; nt++) {
                int col = nt * 8 + 2 * tig;
                float lx = c[nt][0], ly = c[nt][1], hx = c[nt][2], hy = c[nt][3];
                if (relu) {
                    lx = fmaxf(lx, 0.f); ly = fmaxf(ly, 0.f);
                    hx = fmaxf(hx, 0.f); hy = fmaxf(hy, 0.f);
                }
                *(unsigned*)&O[(size_t)row0 * D + col]       = packh(lx, ly);
                *(unsigned*)&O[(size_t)(row0 + 8) * D + col] = packh(hx, hy);
                c[nt][0] = 0.f; c[nt][1] = 0.f; c[nt][2] = 0.f; c[nt][3] = 0.f;
            }
        }
        buf ^= 1;
    }
}

// ---------------- fused FFN: out = sa + relu(h@w1^T+b1)@w2^T + b2 --------------
__global__ __launch_bounds__(256) void ffn_kernel(const float* __restrict__ A,
        const float* __restrict__ W1, const float* __restrict__ W2,
        const float* __restrict__ b1v, const float* __restrict__ b2v,
        const float* __restrict__ res, float* __restrict__ out) {
    extern __shared__ float sm[];
    float* sA = sm;
    float* sW0 = sm + 128 * ASTR;
    float* sW1 = sW0 + 128 * WSTR;
    int tid = threadIdx.x, warp = tid >> 5, lane = tid & 31;
    int g = lane >> 2, tig = lane & 3;
    int rowBase = blockIdx.x * 128;

    for (int i = tid; i < 128 * 32; i += 256) {
        int r = i >> 5, c4 = (i & 31) * 4;
        CPA16(s2u(sA + r * ASTR + c4), &A[(size_t)(rowBase + r) * D + c4], 16);
    }
    CPC();
    for (int i = tid; i < 128 * 8; i += 256) {
        int n = i >> 3, seg = (i & 7) * 4;
        CPA16(s2u(sW0 + n * WSTR + seg), &W1[(size_t)n * D + seg], 16);
    }
    CPC();

    unsigned aBase = s2u(sA) +
        (((warp * 16 + (lane & 7) + ((lane >> 3) & 1) * 8) * ASTR + (lane >> 4) * 4) << 2);
    unsigned wOff =
        ((((lane & 7) + (lane >> 4) * 8) * WSTR + ((lane >> 3) & 1) * 4) << 2);
    unsigned wBase[2] = { s2u(sW0) + wOff, s2u(sW1) + wOff };

    float c[16][4] = {};
    int buf = 0;

    #pragma unroll
    for (int t = 0; t < 8; t++) {
        int kc = t & 3;
        __syncthreads();
        if (t + 1 < 8) {
            const float* Wn = (t + 1 < 4) ? W1 : W2;
            int kcn = (t + 1) & 3;
            float* dst = buf ? sW0 : sW1;
            for (int i = tid; i < 128 * 8; i += 256) {
                int n = i >> 3, seg = (i & 7) * 4;
                CPA16(s2u(dst + n * WSTR + seg), &Wn[(size_t)n * D + kcn * 32 + seg], 16);
            }
            CPC();
            CPW1();
        } else {
            CPW0();
        }
        __syncthreads();

        #pragma unroll
        for (int k8 = 0; k8 < 4; k8++) {
            unsigned a[4];
            LDSM_X4(a, aBase + kc * 128 + k8 * 32);
            #pragma unroll
            for (int np = 0; np < 8; np++) {
                unsigned bb[4];
                LDSM_X4(bb, wBase[buf] + np * (16 * WSTR * 4) + k8 * 32);
                MMA_TF32(c[np*2],     a, bb[0], bb[1]);
                MMA_TF32(c[np*2 + 1], a, bb[2], bb[3]);
            }
        }

        if (t == 3) {
            __syncthreads();     // everyone done reading phase-1 A
            int row0l = warp * 16 + g;
            #pragma unroll
            for (int nt = 0; nt < 16; nt++) {
                int col = nt * 8 + 2 * tig;
                float2 bb = *(const float2*)&b1v[col];
                float2 lo, hi;
                lo.x = __uint_as_float(tf32r(fmaxf(c[nt][0] + bb.x, 0.f)));
                lo.y = __uint_as_float(tf32r(fmaxf(c[nt][1] + bb.y, 0.f)));
                hi.x = __uint_as_float(tf32r(fmaxf(c[nt][2] + bb.x, 0.f)));
                hi.y = __uint_as_float(tf32r(fmaxf(c[nt][3] + bb.y, 0.f)));
                *(float2*)&sA[row0l * ASTR + col] = lo;
                *(float2*)&sA[(row0l + 8) * ASTR + col] = hi;
                c[nt][0] = 0.f; c[nt][1] = 0.f; c[nt][2] = 0.f; c[nt][3] = 0.f;
            }
        }
        if (t == 7) {
            int row0 = rowBase + warp * 16 + g;
            #pragma unroll
            for (int nt = 0; nt < 16; nt++) {
                int col = nt * 8 + 2 * tig;
                float2 bb = *(const float2*)&b2v[col];
                float2 r0v = *(const float2*)&res[(size_t)row0 * D + col];
                float2 r1v = *(const float2*)&res[(size_t)(row0 + 8) * D + col];
                float2 lo = make_float2(c[nt][0] + bb.x + r0v.x, c[nt][1] + bb.y + r0v.y);
                float2 hi = make_float2(c[nt][2] + bb.x + r1v.x, c[nt][3] + bb.y + r1v.y);
                *(float2*)&out[(size_t)row0 * D + col] = lo;
                *(float2*)&out[(size_t)(row0 + 8) * D + col] = hi;
            }
        }
        buf ^= 1;
    }
}

// ---------------- fp16 flash attention: 4-stage ring, pair-unrolled ------------
// Max-free softmax; row-sums via constant ones B-fragment MMA; two k-tiles per
// iteration with ONE barrier per pair -> S/exp/PV of the two tiles interleave
// (ILP) and warp phases decohere. Epilogue fuses sa = xn + attn.
#define AKS 40
__shared__ __half sAK[4][64][AKS];
__shared__ __half sAV[4][64][AKS];

__device__ __forceinline__ void tile_S(unsigned kAddr, const unsigned qa[2][4],
                                       int kv, int tig, unsigned* p01, unsigned* p23) {
    #pragma unroll
    for (int nt = 0; nt < 8; nt++) {
        float sarr[4] = {0.f, 0.f, 0.f, 0.f};
        unsigned kf[4];
        LDSM_X4(kf, kAddr + nt * 8 * AKS * 2);
        MMA_F16(sarr, qa[0], kf[0], kf[1]);
        MMA_F16(sarr, qa[1], kf[2], kf[3]);
        if (kv < 64) {
            int col = nt * 8 + 2 * tig;
            if (col     >= kv) { sarr[0] = -1000.f; sarr[2] = -1000.f; }
            if (col + 1 >= kv) { sarr[1] = -1000.f; sarr[3] = -1000.f; }
        }
        p01[nt] = h2exp2(sarr[0], sarr[1]);
        p23[nt] = h2exp2(sarr[2], sarr[3]);
    }
}

__device__ __forceinline__ void tile_PV(unsigned vAddr, const unsigned* p01,
                                        const unsigned* p23, unsigned onesb,
                                        float o[5][4]) {
    #pragma unroll
    for (int ksp = 0; ksp < 4; ksp++) {
        unsigned pa[4] = { p01[2*ksp], p23[2*ksp], p01[2*ksp+1], p23[2*ksp+1] };
        #pragma unroll
        for (int dh = 0; dh < 2; dh++) {
            unsigned vb[4];
            LDSM_X4_T(vb, vAddr + (ksp * 16 * AKS + dh * 16) * 2);
            MMA_F16(o[dh*2 + 0], pa, vb[0], vb[1]);
            MMA_F16(o[dh*2 + 1], pa, vb[2], vb[3]);
        }
        MMA_F16(o[4], pa, onesb, onesb);
    }
}

__global__ __launch_bounds__(256) void attn_f16_kernel(
        const __half* __restrict__ gqh, const __half* __restrict__ gkh,
        const __half* __restrict__ gvh, const int* __restrict__ idx,
        const int* __restrict__ cnt, const float* __restrict__ xn,
        float* __restrict__ sa) {
    int tid = threadIdx.x;
    int warp = tid >> 5, lane = tid & 31;
    int g = lane >> 2, tig = lane & 3;
    int b = blockIdx.y >> 2, h = blockIdx.y & 3;
    int q0 = blockIdx.x * 128 + warp * 16;
    int nb = cnt[b];
    const int* bidx = idx + b * SEQ;
    int ntiles = (nb + 63) >> 6;

    unsigned onesb = (lane < 4) ? 0x3C003C00u : 0u;

    // Q fragments
    const float qs = 0.17677669529663687f * 1.4426950408889634f;
    const __half* qp0 = gqh + (size_t)(b * SEQ + q0 + g) * D + h * DK;
    const __half* qp1 = qp0 + 8 * D;
    unsigned qa[2][4];
    #pragma unroll
    for (int ks = 0; ks < 2; ks++) {
        int base = ks * 16 + 2 * tig;
        qa[ks][0] = packh(__half2float(qp0[base]) * qs,     __half2float(qp0[base + 1]) * qs);
        qa[ks][1] = packh(__half2float(qp1[base]) * qs,     __half2float(qp1[base + 1]) * qs);
        qa[ks][2] = packh(__half2float(qp0[base + 8]) * qs, __half2float(qp0[base + 9]) * qs);
        qa[ks][3] = packh(__half2float(qp1[base + 8]) * qs, __half2float(qp1[base + 9]) * qs);
    }

    float o[5][4] = {};

    // fill mapping: 4 threads per key, 16B each
    int fKey = tid >> 2, fSeg = (tid & 3) * 8;
    const __half* kSrc = gkh + (size_t)b * SEQ * D + h * DK + fSeg;
    const __half* vSrc = gvh + (size_t)b * SEQ * D + h * DK + fSeg;

    // per-stage addresses
    int kRow = lane & 7, kCol = (lane >> 3) * 8;
    int vKey = ((lane >> 3) & 1) * 8 + (lane & 7);
    int vCol = (lane >> 4) * 8;
    unsigned kA0 = s2u(&sAK[0][kRow][kCol]), kA1 = s2u(&sAK[1][kRow][kCol]);
    unsigned kA2 = s2u(&sAK[2][kRow][kCol]), kA3 = s2u(&sAK[3][kRow][kCol]);
    unsigned vA0 = s2u(&sAV[0][vKey][vCol]), vA1 = s2u(&sAV[1][vKey][vCol]);
    unsigned vA2 = s2u(&sAV[2][vKey][vCol]), vA3 = s2u(&sAV[3][vKey][vCol]);
    unsigned kD0 = s2u(&sAK[0][fKey][fSeg]), kD1 = s2u(&sAK[1][fKey][fSeg]);
    unsigned kD2 = s2u(&sAK[2][fKey][fSeg]), kD3 = s2u(&sAK[3][fKey][fSeg]);
    unsigned vD0 = s2u(&sAV[0][fKey][fSeg]), vD1 = s2u(&sAV[1][fKey][fSeg]);
    unsigned vD2 = s2u(&sAV[2][fKey][fSeg]), vD3 = s2u(&sAV[3][fKey][fSeg]);

    // prologue: prefetch tiles 0,1 into stages 0,1
    {
        int rem0 = nb, rem1 = nb - 64;
        int pA = (fKey < rem0) ? 16 : 0;
        int giA = (fKey < rem0) ? bidx[fKey] : 0;
        CPA16(kD0, kSrc + (size_t)giA * D, pA);
        CPA16(vD0, vSrc + (size_t)giA * D, pA);
        CPC();
        int pB = (fKey < rem1) ? 16 : 0;
        int giB = (fKey < rem1) ? bidx[64 + fKey] : 0;
        CPA16(kD1, kSrc + (size_t)giB * D, pB);
        CPA16(vD1, vSrc + (size_t)giB * D, pB);
        CPC();
    }

    unsigned p01a[8], p23a[8], p01b[8], p23b[8];
    int t = 0, pb = 0;
    while (t + 1 < ntiles) {
        CPW0();                  // tiles t, t+1 arrived (this thread's groups)
        __syncthreads();         // visibility + all done with stages being reused
        // prefetch tiles t+2, t+3 into the other stage pair
        {
            int kbn = (t + 2) * 64;
            int rem0 = nb - kbn, rem1 = rem0 - 64;
            unsigned kd0 = pb ? kD0 : kD2, vd0 = pb ? vD0 : vD2;
            unsigned kd1 = pb ? kD1 : kD3, vd1 = pb ? vD1 : vD3;
            int pA = (fKey < rem0) ? 16 : 0;
            int giA = (fKey < rem0) ? bidx[kbn + fKey] : 0;
            CPA16(kd0, kSrc + (size_t)giA * D, pA);
            CPA16(vd0, vSrc + (size_t)giA * D, pA);
            CPC();
            int pB = (fKey < rem1) ? 16 : 0;
            int giB = (fKey < rem1) ? bidx[kbn + 64 + fKey] : 0;
            CPA16(kd1, kSrc + (size_t)giB * D, pB);
            CPA16(vd1, vSrc + (size_t)giB * D, pB);
            CPC();
        }
        unsigned ka0 = pb ? kA2 : kA0, ka1 = pb ? kA3 : kA1;
        unsigned va0 = pb ? vA2 : vA0, va1 = pb ? vA3 : vA1;
        int kv1 = min(64, nb - (t + 1) * 64);
        tile_S(ka0, qa, 64, tig, p01a, p23a);
        tile_S(ka1, qa, kv1, tig, p01b, p23b);
        tile_PV(va0, p01a, p23a, onesb, o);
        tile_PV(va1, p01b, p23b, onesb, o);
        t += 2; pb ^= 1;
    }
    if (t < ntiles) {            // odd tail tile
        CPW0();
        __syncthreads();
        unsigned ka0 = pb ? kA2 : kA0;
        unsigned va0 = pb ? vA2 : vA0;
        int kv = nb - t * 64;
        tile_S(ka0, qa, kv, tig, p01a, p23a);
        tile_PV(va0, p01a, p23a, onesb, o);
    }

    // epilogue: sa = xn + O/l  (l in tile col 0, tig==0 lanes)
    float l0 = __shfl_sync(0xffffffffu, o[4][0], lane & 28);
    float l1 = __shfl_sync(0xffffffffu, o[4][2], lane & 28);
    float inv0 = (l0 > 0.f) ? 1.f / l0 : 0.f;
    float inv1 = (l1 > 0.f) ? 1.f / l1 : 0.f;
    const float* xp0 = xn + (size_t)(b * SEQ + q0 + g) * D + h * DK;
    const float* xp1 = xp0 + 8 * D;
    float* op0 = sa + (size_t)(b * SEQ + q0 + g) * D + h * DK;
    float* op1 = op0 + 8 * D;
    #pragma unroll
    for (int nt = 0; nt < 4; nt++) {
        int col = nt * 8 + 2 * tig;
        float2 x0 = *(const float2*)(xp0 + col);
        float2 x1 = *(const float2*)(xp1 + col);
        *(float2*)(op0 + col) = make_float2(o[nt][0] * inv0 + x0.x, o[nt][1] * inv0 + x0.y);
        *(float2*)(op1 + col) = make_float2(o[nt][2] * inv1 + x1.x, o[nt][3] * inv1 + x1.y);
    }
}

// ---------------- launch ---------------------------------------------------------
extern "C" void kernel_launch(void* const* d_in, const int* in_sizes, int n_in,
                              void* d_out, int out_size) {
    const float* x    = (const float*)d_in[0];
    const int*   mask = (const int*)  d_in[1];
    const float* ln_w = (const float*)d_in[2];
    const float* ln_b = (const float*)d_in[3];
    const float* wq   = (const float*)d_in[4];
    const float* wk   = (const float*)d_in[5];
    const float* wv   = (const float*)d_in[6];
    const float* w1   = (const float*)d_in[7];
    const float* b1   = (const float*)d_in[8];
    const float* w2   = (const float*)d_in[9];
    const float* b2   = (const float*)d_in[10];
    float* out = (float*)d_out;

    float *xn, *sa, *h, *wr;
    int *cntp, *idxp;
    __half *qh, *kh, *vh;
    cudaGetSymbolAddress((void**)&xn,   g_xn);
    cudaGetSymbolAddress((void**)&sa,   g_sa);
    cudaGetSymbolAddress((void**)&h,    g_h);
    cudaGetSymbolAddress((void**)&wr,   g_wr);
    cudaGetSymbolAddress((void**)&cntp, g_cnt);
    cudaGetSymbolAddress((void**)&idxp, g_idx);
    cudaGetSymbolAddress((void**)&qh,   g_qh);
    cudaGetSymbolAddress((void**)&kh,   g_kh);
    cudaGetSymbolAddress((void**)&vh,   g_vh);

    cudaFuncSetAttribute(qkv_kernel, cudaFuncAttributeMaxDynamicSharedMemorySize, GEMM_SMEM);
    cudaFuncSetAttribute(ffn_kernel, cudaFuncAttributeMaxDynamicSharedMemorySize, GEMM_SMEM);

    // 0) compact key indices + tf32-round weights
    prep_kernel<<<96, 1024>>>(mask, idxp, cntp, wq, wk, wv, w1, w2, wr);
    // 1) xn = LN(x), tf32-rounded
    ln_kernel<true><<<ROWS/16, 256>>>(x, nullptr, nullptr, xn, ln_w, ln_b);
    // 2) fused QKV -> fp16
    qkv_kernel<<<ROWS/128, 256, GEMM_SMEM>>>(xn, wr, wr + 16384, wr + 32768, qh, kh, vh);
    // 3) attention (writes sa = xn + attn) — profiled launch slot
    attn_f16_kernel<<<dim3(SEQ/128, BATCH*H), 256>>>(qh, kh, vh, idxp, cntp, xn, sa);
    // 4) h = LN(sa), tf32-rounded
    ln_kernel<true><<<ROWS/16, 256>>>(sa, nullptr, nullptr, h, ln_w, ln_b);
    // 5) fused FFN: out = sa + relu(h@w1^T+b1)@w2^T + b2
    ffn_kernel<<<ROWS/128, 256, GEMM_SMEM>>>(h, wr + 49152, wr + 65536, b1, b2, sa, out);
}

// round 12
// speedup vs baseline: 1.0139x; 1.0139x over previous
#include <cuda_runtime.h>
#include <cuda_bf16.h>
#include <cuda_fp16.h>
#include <math.h>

#define D 128
#define H 4
#define DK 32
#define BATCH 16
#define SEQ 2048
#define ROWS (BATCH*SEQ)   // 32768
#define LNEPS 1e-5f

// ---------------- scratch (static device globals; no allocs allowed) ----------
__device__ float g_xn[ROWS*D];
__device__ float g_sa[ROWS*D];
__device__ float g_h [ROWS*D];
__device__ float g_wr[5*D*D];             // tf32-rounded weights (q,k,v,w1,w2)
__device__ int   g_cnt[BATCH];
__device__ int   g_idx[BATCH*SEQ];
__device__ __half g_qh[ROWS*D];           // fp16 Q (relu'd)
__device__ __half g_kh[ROWS*D];           // fp16 K
__device__ __half g_vh[ROWS*D];           // fp16 V

// ---------------- helpers ------------------------------------------------------
__device__ __forceinline__ unsigned tf32r(float x) {
    unsigned u;
    asm("cvt.rna.tf32.f32 %0, %1;" : "=r"(u) : "f"(x));
    return u;
}
__device__ __forceinline__ unsigned packh(float a, float b) {
    __half2 t = __floats2half2_rn(a, b);
    return *(unsigned*)&t;
}
__device__ __forceinline__ unsigned h2exp2(float a, float b) {
    unsigned u = packh(a, b), r;
    asm("ex2.approx.f16x2 %0, %1;" : "=r"(r) : "r"(u));
    return r;
}

#define MMA_TF32(c, a, b0, b1) \
    asm volatile("mma.sync.aligned.m16n8k8.row.col.f32.tf32.tf32.f32 " \
        "{%0,%1,%2,%3}, {%4,%5,%6,%7}, {%8,%9}, {%0,%1,%2,%3};" \
        : "+f"(c[0]), "+f"(c[1]), "+f"(c[2]), "+f"(c[3]) \
        : "r"(a[0]), "r"(a[1]), "r"(a[2]), "r"(a[3]), "r"(b0), "r"(b1))

#define MMA_F16(c, a, b0, b1) \
    asm volatile("mma.sync.aligned.m16n8k16.row.col.f32.f16.f16.f32 " \
        "{%0,%1,%2,%3}, {%4,%5,%6,%7}, {%8,%9}, {%0,%1,%2,%3};" \
        : "+f"(c[0]), "+f"(c[1]), "+f"(c[2]), "+f"(c[3]) \
        : "r"(a[0]), "r"(a[1]), "r"(a[2]), "r"(a[3]), "r"(b0), "r"(b1))

#define LDSM_X4(r, addr) \
    asm volatile("ldmatrix.sync.aligned.m8n8.x4.shared.b16 {%0,%1,%2,%3}, [%4];" \
        : "=r"(r[0]), "=r"(r[1]), "=r"(r[2]), "=r"(r[3]) : "r"(addr))

#define LDSM_X4_T(r, addr) \
    asm volatile("ldmatrix.sync.aligned.m8n8.x4.trans.shared.b16 {%0,%1,%2,%3}, [%4];" \
        : "=r"(r[0]), "=r"(r[1]), "=r"(r[2]), "=r"(r[3]) : "r"(addr))

#define CPA16(dst, src, pbytes) \
    asm volatile("cp.async.cg.shared.global [%0], [%1], 16, %2;" \
        :: "r"(dst), "l"(src), "r"(pbytes))
#define CPC() asm volatile("cp.async.commit_group;" ::: "memory")
#define CPW0() asm volatile("cp.async.wait_group 0;" ::: "memory")
#define CPW1() asm volatile("cp.async.wait_group 1;" ::: "memory")

__device__ __forceinline__ unsigned s2u(const void* p) {
    return (unsigned)__cvta_generic_to_shared(p);
}

// ---------------- LayerNorm: half-warp per row; optional tf32-rounded output ---
template<bool RND>
__global__ void ln_kernel(const float* __restrict__ in,
                          float* __restrict__ ln_out,
                          const float* __restrict__ w, const float* __restrict__ b) {
    int row = blockIdx.x * 16 + (threadIdx.x >> 4);
    int l   = threadIdx.x & 15;
    const float4* ip = (const float4*)(in + (size_t)row * D);
    float4 v0 = ip[l*2], v1 = ip[l*2+1];
    float s = v0.x+v0.y+v0.z+v0.w + v1.x+v1.y+v1.z+v1.w;
    #pragma unroll
    for (int o = 8; o; o >>= 1) s += __shfl_xor_sync(0xffffffffu, s, o);
    float mu = s * (1.0f / D);
    float d0x=v0.x-mu, d0y=v0.y-mu, d0z=v0.z-mu, d0w=v0.w-mu;
    float d1x=v1.x-mu, d1y=v1.y-mu, d1z=v1.z-mu, d1w=v1.w-mu;
    float ss = d0x*d0x+d0y*d0y+d0z*d0z+d0w*d0w + d1x*d1x+d1y*d1y+d1z*d1z+d1w*d1w;
    #pragma unroll
    for (int o = 8; o; o >>= 1) ss += __shfl_xor_sync(0xffffffffu, ss, o);
    float rstd = rsqrtf(ss * (1.0f / D) + LNEPS);
    float4 w0 = ((const float4*)w)[l*2], w1 = ((const float4*)w)[l*2+1];
    float4 b0 = ((const float4*)b)[l*2], b1 = ((const float4*)b)[l*2+1];
    float4 o0, o1;
    o0.x = d0x*rstd*w0.x + b0.x; o0.y = d0y*rstd*w0.y + b0.y;
    o0.z = d0z*rstd*w0.z + b0.z; o0.w = d0w*rstd*w0.w + b0.w;
    o1.x = d1x*rstd*w1.x + b1.x; o1.y = d1y*rstd*w1.y + b1.y;
    o1.z = d1z*rstd*w1.z + b1.z; o1.w = d1w*rstd*w1.w + b1.w;
    if (RND) {
        o0.x = __uint_as_float(tf32r(o0.x)); o0.y = __uint_as_float(tf32r(o0.y));
        o0.z = __uint_as_float(tf32r(o0.z)); o0.w = __uint_as_float(tf32r(o0.w));
        o1.x = __uint_as_float(tf32r(o1.x)); o1.y = __uint_as_float(tf32r(o1.y));
        o1.z = __uint_as_float(tf32r(o1.z)); o1.w = __uint_as_float(tf32r(o1.w));
    }
    float4* op = (float4*)(ln_out + (size_t)row * D);
    op[l*2] = o0; op[l*2+1] = o1;
}

// ---------------- prep: mask compaction + tf32-round all weights ---------------
__global__ void prep_kernel(const int* __restrict__ mask,
                            int* __restrict__ idx, int* __restrict__ cnt,
                            const float* __restrict__ wq, const float* __restrict__ wk,
                            const float* __restrict__ wv, const float* __restrict__ w1,
                            const float* __restrict__ w2, float* __restrict__ wr) {
    __shared__ int wsum[32];
    if (blockIdx.x >= 16) {
        int i = (blockIdx.x - 16) * 1024 + threadIdx.x;
        int which = i >> 14, off = i & 16383;
        const float* srcs[5] = {wq, wk, wv, w1, w2};
        wr[i] = __uint_as_float(tf32r(srcs[which][off]));
        return;
    }
    int b = blockIdx.x, t = threadIdx.x;
    const int* mb = mask + b * SEQ;
    int m0 = mb[2*t], m1 = mb[2*t+1];
    int s = m0 + m1;
    int lane = t & 31, w = t >> 5;
    int v = s;
    #pragma unroll
    for (int o = 1; o < 32; o <<= 1) {
        int u = __shfl_up_sync(0xffffffffu, v, o);
        if (lane >= o) v += u;
    }
    if (lane == 31) wsum[w] = v;
    __syncthreads();
    if (t < 32) {
        int u = wsum[t];
        #pragma unroll
        for (int o = 1; o < 32; o <<= 1) {
            int x = __shfl_up_sync(0xffffffffu, u, o);
            if (t >= o) u += x;
        }
        wsum[t] = u;
    }
    __syncthreads();
    int p = v - s + (w ? wsum[w-1] : 0);
    if (m0) idx[b*SEQ + p++] = 2*t;
    if (m1) idx[b*SEQ + p]   = 2*t + 1;
    if (t == 1023) cnt[b] = wsum[31];
}

// ---------------- pipelined tf32 GEMM (QKV): A resident, W streamed, fp16 out --
#define ASTR 132
#define WSTR 36
#define GEMM_SMEM (128*ASTR*4 + 2*128*WSTR*4)   // 104448 B

__global__ __launch_bounds__(256) void qkv_kernel(const float* __restrict__ A,
        const float* __restrict__ W0, const float* __restrict__ W1,
        const float* __restrict__ W2,
        __half* __restrict__ O0, __half* __restrict__ O1, __half* __restrict__ O2) {
    extern __shared__ float sm[];
    float* sA = sm;
    float* sW0 = sm + 128 * ASTR;
    float* sW1 = sW0 + 128 * WSTR;
    int tid = threadIdx.x, warp = tid >> 5, lane = tid & 31;
    int g = lane >> 2, tig = lane & 3;
    int rowBase = blockIdx.x * 128;

    const float* Ws[3] = {W0, W1, W2};
    __half* Os[3] = {O0, O1, O2};

    for (int i = tid; i < 128 * 32; i += 256) {
        int r = i >> 5, c4 = (i & 31) * 4;
        CPA16(s2u(sA + r * ASTR + c4), &A[(size_t)(rowBase + r) * D + c4], 16);
    }
    CPC();
    for (int i = tid; i < 128 * 8; i += 256) {
        int n = i >> 3, seg = (i & 7) * 4;
        CPA16(s2u(sW0 + n * WSTR + seg), &W0[(size_t)n * D + seg], 16);
    }
    CPC();

    unsigned aBase = s2u(sA) +
        (((warp * 16 + (lane & 7) + ((lane >> 3) & 1) * 8) * ASTR + (lane >> 4) * 4) << 2);
    unsigned wOff =
        ((((lane & 7) + (lane >> 4) * 8) * WSTR + ((lane >> 3) & 1) * 4) << 2);
    unsigned wBase[2] = { s2u(sW0) + wOff, s2u(sW1) + wOff };

    float c[16][4] = {};
    int buf = 0;

    #pragma unroll
    for (int t = 0; t < 12; t++) {
        int wi = t >> 2, kc = t & 3;
        __syncthreads();
        if (t + 1 < 12) {
            const float* Wn = Ws[(t + 1) >> 2];
            int kcn = (t + 1) & 3;
            float* dst = buf ? sW0 : sW1;
            for (int i = tid; i < 128 * 8; i += 256) {
                int n = i >> 3, seg = (i & 7) * 4;
                CPA16(s2u(dst + n * WSTR + seg), &Wn[(size_t)n * D + kcn * 32 + seg], 16);
            }
            CPC();
            CPW1();
        } else {
            CPW0();
        }
        __syncthreads();

        #pragma unroll
        for (int k8 = 0; k8 < 4; k8++) {
            unsigned a[4];
            LDSM_X4(a, aBase + kc * 128 + k8 * 32);
            #pragma unroll
            for (int np = 0; np < 8; np++) {
                unsigned bb[4];
                LDSM_X4(bb, wBase[buf] + np * (16 * WSTR * 4) + k8 * 32);
                MMA_TF32(c[np*2],     a, bb[0], bb[1]);
                MMA_TF32(c[np*2 + 1], a, bb[2], bb[3]);
            }
        }

        if (kc == 3) {
            __half* O = Os[wi];
            int row0 = rowBase + warp * 16 + g;
            bool relu = (wi == 0);
            #pragma unroll
            for (int nt = 0; nt < 16; nt++) {
                int col = nt * 8 + 2 * tig;
                float lx = c[nt][0], ly = c[nt][1], hx = c[nt][2], hy = c[nt][3];
                if (relu) {
                    lx = fmaxf(lx, 0.f); ly = fmaxf(ly, 0.f);
                    hx = fmaxf(hx, 0.f); hy = fmaxf(hy, 0.f);
                }
                *(unsigned*)&O[(size_t)row0 * D + col]       = packh(lx, ly);
                *(unsigned*)&O[(size_t)(row0 + 8) * D + col] = packh(hx, hy);
                c[nt][0] = 0.f; c[nt][1] = 0.f; c[nt][2] = 0.f; c[nt][3] = 0.f;
            }
        }
        buf ^= 1;
    }
}

// ---------------- fused FFN: out = sa + relu(h@w1^T+b1)@w2^T + b2 --------------
__global__ __launch_bounds__(256) void ffn_kernel(const float* __restrict__ A,
        const float* __restrict__ W1, const float* __restrict__ W2,
        const float* __restrict__ b1v, const float* __restrict__ b2v,
        const float* __restrict__ res, float* __restrict__ out) {
    extern __shared__ float sm[];
    float* sA = sm;
    float* sW0 = sm + 128 * ASTR;
    float* sW1 = sW0 + 128 * WSTR;
    int tid = threadIdx.x, warp = tid >> 5, lane = tid & 31;
    int g = lane >> 2, tig = lane & 3;
    int rowBase = blockIdx.x * 128;

    for (int i = tid; i < 128 * 32; i += 256) {
        int r = i >> 5, c4 = (i & 31) * 4;
        CPA16(s2u(sA + r * ASTR + c4), &A[(size_t)(rowBase + r) * D + c4], 16);
    }
    CPC();
    for (int i = tid; i < 128 * 8; i += 256) {
        int n = i >> 3, seg = (i & 7) * 4;
        CPA16(s2u(sW0 + n * WSTR + seg), &W1[(size_t)n * D + seg], 16);
    }
    CPC();

    unsigned aBase = s2u(sA) +
        (((warp * 16 + (lane & 7) + ((lane >> 3) & 1) * 8) * ASTR + (lane >> 4) * 4) << 2);
    unsigned wOff =
        ((((lane & 7) + (lane >> 4) * 8) * WSTR + ((lane >> 3) & 1) * 4) << 2);
    unsigned wBase[2] = { s2u(sW0) + wOff, s2u(sW1) + wOff };

    float c[16][4] = {};
    int buf = 0;

    #pragma unroll
    for (int t = 0; t < 8; t++) {
        int kc = t & 3;
        __syncthreads();
        if (t + 1 < 8) {
            const float* Wn = (t + 1 < 4) ? W1 : W2;
            int kcn = (t + 1) & 3;
            float* dst = buf ? sW0 : sW1;
            for (int i = tid; i < 128 * 8; i += 256) {
                int n = i >> 3, seg = (i & 7) * 4;
                CPA16(s2u(dst + n * WSTR + seg), &Wn[(size_t)n * D + kcn * 32 + seg], 16);
            }
            CPC();
            CPW1();
        } else {
            CPW0();
        }
        __syncthreads();

        #pragma unroll
        for (int k8 = 0; k8 < 4; k8++) {
            unsigned a[4];
            LDSM_X4(a, aBase + kc * 128 + k8 * 32);
            #pragma unroll
            for (int np = 0; np < 8; np++) {
                unsigned bb[4];
                LDSM_X4(bb, wBase[buf] + np * (16 * WSTR * 4) + k8 * 32);
                MMA_TF32(c[np*2],     a, bb[0], bb[1]);
                MMA_TF32(c[np*2 + 1], a, bb[2], bb[3]);
            }
        }

        if (t == 3) {
            __syncthreads();     // everyone done reading phase-1 A
            int row0l = warp * 16 + g;
            #pragma unroll
            for (int nt = 0; nt < 16; nt++) {
                int col = nt * 8 + 2 * tig;
                float2 bb = *(const float2*)&b1v[col];
                float2 lo, hi;
                lo.x = __uint_as_float(tf32r(fmaxf(c[nt][0] + bb.x, 0.f)));
                lo.y = __uint_as_float(tf32r(fmaxf(c[nt][1] + bb.y, 0.f)));
                hi.x = __uint_as_float(tf32r(fmaxf(c[nt][2] + bb.x, 0.f)));
                hi.y = __uint_as_float(tf32r(fmaxf(c[nt][3] + bb.y, 0.f)));
                *(float2*)&sA[row0l * ASTR + col] = lo;
                *(float2*)&sA[(row0l + 8) * ASTR + col] = hi;
                c[nt][0] = 0.f; c[nt][1] = 0.f; c[nt][2] = 0.f; c[nt][3] = 0.f;
            }
        }
        if (t == 7) {
            int row0 = rowBase + warp * 16 + g;
            #pragma unroll
            for (int nt = 0; nt < 16; nt++) {
                int col = nt * 8 + 2 * tig;
                float2 bb = *(const float2*)&b2v[col];
                float2 r0v = *(const float2*)&res[(size_t)row0 * D + col];
                float2 r1v = *(const float2*)&res[(size_t)(row0 + 8) * D + col];
                float2 lo = make_float2(c[nt][0] + bb.x + r0v.x, c[nt][1] + bb.y + r0v.y);
                float2 hi = make_float2(c[nt][2] + bb.x + r1v.x, c[nt][3] + bb.y + r1v.y);
                *(float2*)&out[(size_t)row0 * D + col] = lo;
                *(float2*)&out[(size_t)(row0 + 8) * D + col] = hi;
            }
        }
        buf ^= 1;
    }
}

// ---------------- fp16 flash attention: 2-stage, max-free, MMA row-sums --------
// Round-10 structure (80 regs, 20KB smem, 3 CTA/SM) + fused sa = xn + attn
// epilogue. Max-free softmax (scores O(1)); P via ex2.approx.f16x2; row-sums l
// via constant ones B-fragment MMA.
#define AKS 40
__global__ __launch_bounds__(256) void attn_f16_kernel(
        const __half* __restrict__ gqh, const __half* __restrict__ gkh,
        const __half* __restrict__ gvh, const int* __restrict__ idx,
        const int* __restrict__ cnt, const float* __restrict__ xn,
        float* __restrict__ sa) {
    __shared__ __half sK[2][64][AKS];
    __shared__ __half sV[2][64][AKS];

    int tid = threadIdx.x;
    int warp = tid >> 5, lane = tid & 31;
    int g = lane >> 2, tig = lane & 3;
    int b = blockIdx.y >> 2, h = blockIdx.y & 3;
    int q0 = blockIdx.x * 128 + warp * 16;
    int nb = cnt[b];
    const int* bidx = idx + b * SEQ;

    unsigned onesb = (lane < 4) ? 0x3C003C00u : 0u;

    const float qs = 0.17677669529663687f * 1.4426950408889634f;
    const __half* qp0 = gqh + (size_t)(b * SEQ + q0 + g) * D + h * DK;
    const __half* qp1 = qp0 + 8 * D;
    unsigned qa[2][4];
    #pragma unroll
    for (int ks = 0; ks < 2; ks++) {
        int base = ks * 16 + 2 * tig;
        qa[ks][0] = packh(__half2float(qp0[base]) * qs,     __half2float(qp0[base + 1]) * qs);
        qa[ks][1] = packh(__half2float(qp1[base]) * qs,     __half2float(qp1[base + 1]) * qs);
        qa[ks][2] = packh(__half2float(qp0[base + 8]) * qs, __half2float(qp0[base + 9]) * qs);
        qa[ks][3] = packh(__half2float(qp1[base + 8]) * qs, __half2float(qp1[base + 9]) * qs);
    }

    float o[5][4] = {};          // [0..3]: O d-tiles; [4]: l tile (col 0)

    int fKey = tid >> 2, fSeg = (tid & 3) * 8;
    size_t headOff = (size_t)b * SEQ * D + h * DK + fSeg;

    int kRow = lane & 7, kCol = (lane >> 3) * 8;
    int vKey = ((lane >> 3) & 1) * 8 + (lane & 7);
    int vCol = (lane >> 4) * 8;
    unsigned vB[2] = { s2u(&sV[0][vKey][vCol]), s2u(&sV[1][vKey][vCol]) };

    {
        int p = (fKey < nb) ? 16 : 0;
        int gi = (fKey < nb) ? bidx[fKey] : 0;
        CPA16(s2u(&sK[0][fKey][fSeg]), gkh + headOff + (size_t)gi * D, p);
        CPA16(s2u(&sV[0][fKey][fSeg]), gvh + headOff + (size_t)gi * D, p);
        CPC();
    }

    int buf = 0;
    for (int kb = 0; kb < nb; kb += 64, buf ^= 1) {
        int kv = min(64, nb - kb);
        CPW0();
        __syncthreads();
        if (kb + 64 < nb) {
            int rem = nb - (kb + 64);
            int p = (fKey < rem) ? 16 : 0;
            int gi = (fKey < rem) ? bidx[kb + 64 + fKey] : 0;
            CPA16(s2u(&sK[buf ^ 1][fKey][fSeg]), gkh + headOff + (size_t)gi * D, p);
            CPA16(s2u(&sV[buf ^ 1][fKey][fSeg]), gvh + headOff + (size_t)gi * D, p);
            CPC();
        }

        unsigned kAddr = s2u(&sK[buf][kRow][kCol]);

        // S = Q K^T
        float s[8][4];
        #pragma unroll
        for (int nt = 0; nt < 8; nt++) {
            s[nt][0] = 0.f; s[nt][1] = 0.f; s[nt][2] = 0.f; s[nt][3] = 0.f;
            unsigned kf[4];
            LDSM_X4(kf, kAddr + nt * 8 * AKS * 2);
            MMA_F16(s[nt], qa[0], kf[0], kf[1]);
            MMA_F16(s[nt], qa[1], kf[2], kf[3]);
        }

        if (kv < 64) {
            #pragma unroll
            for (int nt = 0; nt < 8; nt++) {
                int col = nt * 8 + 2 * tig;
                if (col     >= kv) { s[nt][0] = -1000.f; s[nt][2] = -1000.f; }
                if (col + 1 >= kv) { s[nt][1] = -1000.f; s[nt][3] = -1000.f; }
            }
        }

        // P = exp2(S): two scores per MUFU op, pre-packed f16x2
        unsigned p01[8], p23[8];
        #pragma unroll
        for (int nt = 0; nt < 8; nt++) {
            p01[nt] = h2exp2(s[nt][0], s[nt][1]);
            p23[nt] = h2exp2(s[nt][2], s[nt][3]);
        }

        // O += P V ; l += P 1
        #pragma unroll
        for (int ksp = 0; ksp < 4; ksp++) {
            unsigned pa[4] = { p01[2*ksp], p23[2*ksp], p01[2*ksp+1], p23[2*ksp+1] };
            #pragma unroll
            for (int dh = 0; dh < 2; dh++) {
                unsigned vb[4];
                LDSM_X4_T(vb, vB[buf] + (ksp * 16 * AKS + dh * 16) * 2);
                MMA_F16(o[dh*2 + 0], pa, vb[0], vb[1]);
                MMA_F16(o[dh*2 + 1], pa, vb[2], vb[3]);
            }
            MMA_F16(o[4], pa, onesb, onesb);
        }
    }

    // epilogue: sa = xn + O/l  (l in tile col 0, tig==0 lanes)
    float l0 = __shfl_sync(0xffffffffu, o[4][0], lane & 28);
    float l1 = __shfl_sync(0xffffffffu, o[4][2], lane & 28);
    float inv0 = (l0 > 0.f) ? 1.f / l0 : 0.f;
    float inv1 = (l1 > 0.f) ? 1.f / l1 : 0.f;
    const float* xp0 = xn + (size_t)(b * SEQ + q0 + g) * D + h * DK;
    const float* xp1 = xp0 + 8 * D;
    float* op0 = sa + (size_t)(b * SEQ + q0 + g) * D + h * DK;
    float* op1 = op0 + 8 * D;
    #pragma unroll
    for (int nt = 0; nt < 4; nt++) {
        int col = nt * 8 + 2 * tig;
        float2 x0 = *(const float2*)(xp0 + col);
        float2 x1 = *(const float2*)(xp1 + col);
        *(float2*)(op0 + col) = make_float2(o[nt][0] * inv0 + x0.x, o[nt][1] * inv0 + x0.y);
        *(float2*)(op1 + col) = make_float2(o[nt][2] * inv1 + x1.x, o[nt][3] * inv1 + x1.y);
    }
}

// ---------------- launch ---------------------------------------------------------
extern "C" void kernel_launch(void* const* d_in, const int* in_sizes, int n_in,
                              void* d_out, int out_size) {
    const float* x    = (const float*)d_in[0];
    const int*   mask = (const int*)  d_in[1];
    const float* ln_w = (const float*)d_in[2];
    const float* ln_b = (const float*)d_in[3];
    const float* wq   = (const float*)d_in[4];
    const float* wk   = (const float*)d_in[5];
    const float* wv   = (const float*)d_in[6];
    const float* w1   = (const float*)d_in[7];
    const float* b1   = (const float*)d_in[8];
    const float* w2   = (const float*)d_in[9];
    const float* b2   = (const float*)d_in[10];
    float* out = (float*)d_out;

    float *xn, *sa, *h, *wr;
    int *cntp, *idxp;
    __half *qh, *kh, *vh;
    cudaGetSymbolAddress((void**)&xn,   g_xn);
    cudaGetSymbolAddress((void**)&sa,   g_sa);
    cudaGetSymbolAddress((void**)&h,    g_h);
    cudaGetSymbolAddress((void**)&wr,   g_wr);
    cudaGetSymbolAddress((void**)&cntp, g_cnt);
    cudaGetSymbolAddress((void**)&idxp, g_idx);
    cudaGetSymbolAddress((void**)&qh,   g_qh);
    cudaGetSymbolAddress((void**)&kh,   g_kh);
    cudaGetSymbolAddress((void**)&vh,   g_vh);

    cudaFuncSetAttribute(qkv_kernel, cudaFuncAttributeMaxDynamicSharedMemorySize, GEMM_SMEM);
    cudaFuncSetAttribute(ffn_kernel, cudaFuncAttributeMaxDynamicSharedMemorySize, GEMM_SMEM);

    // 0) compact key indices + tf32-round weights
    prep_kernel<<<96, 1024>>>(mask, idxp, cntp, wq, wk, wv, w1, w2, wr);
    // 1) xn = LN(x), tf32-rounded
    ln_kernel<true><<<ROWS/16, 256>>>(x, xn, ln_w, ln_b);
    // 2) fused QKV -> fp16
    qkv_kernel<<<ROWS/128, 256, GEMM_SMEM>>>(xn, wr, wr + 16384, wr + 32768, qh, kh, vh);
    // 3) attention (writes sa = xn + attn) — profiled launch slot
    attn_f16_kernel<<<dim3(SEQ/128, BATCH*H), 256>>>(qh, kh, vh, idxp, cntp, xn, sa);
    // 4) h = LN(sa), tf32-rounded
    ln_kernel<true><<<ROWS/16, 256>>>(sa, h, ln_w, ln_b);
    // 5) fused FFN: out = sa + relu(h@w1^T+b1)@w2^T + b2
    ffn_kernel<<<ROWS/128, 256, GEMM_SMEM>>>(h, wr + 49152, wr + 65536, b1, b2, sa, out);
}

// round 13
// speedup vs baseline: 1.0683x; 1.0536x over previous
#include <cuda_runtime.h>
#include <cuda_bf16.h>
#include <cuda_fp16.h>
#include <math.h>

#define D 128
#define H 4
#define DK 32
#define BATCH 16
#define SEQ 2048
#define ROWS (BATCH*SEQ)   // 32768
#define LNEPS 1e-5f

// ---------------- scratch (static device globals; no allocs allowed) ----------
__device__ float g_xn[ROWS*D];
__device__ float g_sa[ROWS*D];
__device__ float g_wr[5*D*D];             // tf32-rounded weights (q,k,v,w1,w2)
__device__ int   g_cnt[BATCH];
__device__ int   g_idx[BATCH*SEQ];
__device__ __half g_qh[ROWS*D];           // fp16 Q (relu'd)
__device__ __half g_kh[ROWS*D];           // fp16 K
__device__ __half g_vh[ROWS*D];           // fp16 V

// ---------------- helpers ------------------------------------------------------
__device__ __forceinline__ unsigned tf32r(float x) {
    unsigned u;
    asm("cvt.rna.tf32.f32 %0, %1;" : "=r"(u) : "f"(x));
    return u;
}
__device__ __forceinline__ unsigned packh(float a, float b) {
    __half2 t = __floats2half2_rn(a, b);
    return *(unsigned*)&t;
}
__device__ __forceinline__ unsigned h2exp2(float a, float b) {
    unsigned u = packh(a, b), r;
    asm("ex2.approx.f16x2 %0, %1;" : "=r"(r) : "r"(u));
    return r;
}

#define MMA_TF32(c, a, b0, b1) \
    asm volatile("mma.sync.aligned.m16n8k8.row.col.f32.tf32.tf32.f32 " \
        "{%0,%1,%2,%3}, {%4,%5,%6,%7}, {%8,%9}, {%0,%1,%2,%3};" \
        : "+f"(c[0]), "+f"(c[1]), "+f"(c[2]), "+f"(c[3]) \
        : "r"(a[0]), "r"(a[1]), "r"(a[2]), "r"(a[3]), "r"(b0), "r"(b1))

#define MMA_F16(c, a, b0, b1) \
    asm volatile("mma.sync.aligned.m16n8k16.row.col.f32.f16.f16.f32 " \
        "{%0,%1,%2,%3}, {%4,%5,%6,%7}, {%8,%9}, {%0,%1,%2,%3};" \
        : "+f"(c[0]), "+f"(c[1]), "+f"(c[2]), "+f"(c[3]) \
        : "r"(a[0]), "r"(a[1]), "r"(a[2]), "r"(a[3]), "r"(b0), "r"(b1))

#define LDSM_X4(r, addr) \
    asm volatile("ldmatrix.sync.aligned.m8n8.x4.shared.b16 {%0,%1,%2,%3}, [%4];" \
        : "=r"(r[0]), "=r"(r[1]), "=r"(r[2]), "=r"(r[3]) : "r"(addr))

#define LDSM_X4_T(r, addr) \
    asm volatile("ldmatrix.sync.aligned.m8n8.x4.trans.shared.b16 {%0,%1,%2,%3}, [%4];" \
        : "=r"(r[0]), "=r"(r[1]), "=r"(r[2]), "=r"(r[3]) : "r"(addr))

#define CPA16(dst, src, pbytes) \
    asm volatile("cp.async.cg.shared.global [%0], [%1], 16, %2;" \
        :: "r"(dst), "l"(src), "r"(pbytes))
#define CPC() asm volatile("cp.async.commit_group;" ::: "memory")
#define CPW0() asm volatile("cp.async.wait_group 0;" ::: "memory")
#define CPW1() asm volatile("cp.async.wait_group 1;" ::: "memory")

__device__ __forceinline__ unsigned s2u(const void* p) {
    return (unsigned)__cvta_generic_to_shared(p);
}

#define ASTR 132
#define WSTR 36
#define GEMM_SMEM (128*ASTR*4 + 2*128*WSTR*4)   // 104448 B

// ---- in-smem LayerNorm of a 128x128 tile (half-warp per row, tf32-rounded) ----
// Each thread owns cols [l*8, l*8+8) of its rows: read/write exclusive, no
// smem hazards. Optionally streams the normalized rows to xn_out (gmem).
__device__ __forceinline__ void ln_tile(float* sA, int rowBase, int tid,
        const float* __restrict__ w, const float* __restrict__ b,
        float* __restrict__ xn_out) {
    int hw = tid >> 4;          // half-warp id 0..15
    int l  = tid & 15;
    float4 w0 = ((const float4*)w)[l*2], w1 = ((const float4*)w)[l*2+1];
    float4 b0 = ((const float4*)b)[l*2], b1 = ((const float4*)b)[l*2+1];
    #pragma unroll
    for (int it = 0; it < 8; it++) {
        int row = it * 16 + hw;
        float4 v0 = *(float4*)&sA[row * ASTR + l*8];
        float4 v1 = *(float4*)&sA[row * ASTR + l*8 + 4];
        float s = v0.x+v0.y+v0.z+v0.w + v1.x+v1.y+v1.z+v1.w;
        #pragma unroll
        for (int o = 8; o; o >>= 1) s += __shfl_xor_sync(0xffffffffu, s, o);
        float mu = s * (1.0f / D);
        float d0x=v0.x-mu, d0y=v0.y-mu, d0z=v0.z-mu, d0w=v0.w-mu;
        float d1x=v1.x-mu, d1y=v1.y-mu, d1z=v1.z-mu, d1w=v1.w-mu;
        float ss = d0x*d0x+d0y*d0y+d0z*d0z+d0w*d0w + d1x*d1x+d1y*d1y+d1z*d1z+d1w*d1w;
        #pragma unroll
        for (int o = 8; o; o >>= 1) ss += __shfl_xor_sync(0xffffffffu, ss, o);
        float rstd = rsqrtf(ss * (1.0f / D) + LNEPS);
        float4 o0, o1;
        o0.x = __uint_as_float(tf32r(d0x*rstd*w0.x + b0.x));
        o0.y = __uint_as_float(tf32r(d0y*rstd*w0.y + b0.y));
        o0.z = __uint_as_float(tf32r(d0z*rstd*w0.z + b0.z));
        o0.w = __uint_as_float(tf32r(d0w*rstd*w0.w + b0.w));
        o1.x = __uint_as_float(tf32r(d1x*rstd*w1.x + b1.x));
        o1.y = __uint_as_float(tf32r(d1y*rstd*w1.y + b1.y));
        o1.z = __uint_as_float(tf32r(d1z*rstd*w1.z + b1.z));
        o1.w = __uint_as_float(tf32r(d1w*rstd*w1.w + b1.w));
        *(float4*)&sA[row * ASTR + l*8]     = o0;
        *(float4*)&sA[row * ASTR + l*8 + 4] = o1;
        if (xn_out) {
            *(float4*)&xn_out[(size_t)(rowBase + row) * D + l*8]     = o0;
            *(float4*)&xn_out[(size_t)(rowBase + row) * D + l*8 + 4] = o1;
        }
    }
}

// ---------------- prep: mask compaction + tf32-round all weights ---------------
__global__ void prep_kernel(const int* __restrict__ mask,
                            int* __restrict__ idx, int* __restrict__ cnt,
                            const float* __restrict__ wq, const float* __restrict__ wk,
                            const float* __restrict__ wv, const float* __restrict__ w1,
                            const float* __restrict__ w2, float* __restrict__ wr) {
    __shared__ int wsum[32];
    if (blockIdx.x >= 16) {
        int i = (blockIdx.x - 16) * 1024 + threadIdx.x;
        int which = i >> 14, off = i & 16383;
        const float* srcs[5] = {wq, wk, wv, w1, w2};
        wr[i] = __uint_as_float(tf32r(srcs[which][off]));
        return;
    }
    int b = blockIdx.x, t = threadIdx.x;
    const int* mb = mask + b * SEQ;
    int m0 = mb[2*t], m1 = mb[2*t+1];
    int s = m0 + m1;
    int lane = t & 31, w = t >> 5;
    int v = s;
    #pragma unroll
    for (int o = 1; o < 32; o <<= 1) {
        int u = __shfl_up_sync(0xffffffffu, v, o);
        if (lane >= o) v += u;
    }
    if (lane == 31) wsum[w] = v;
    __syncthreads();
    if (t < 32) {
        int u = wsum[t];
        #pragma unroll
        for (int o = 1; o < 32; o <<= 1) {
            int x = __shfl_up_sync(0xffffffffu, u, o);
            if (t >= o) u += x;
        }
        wsum[t] = u;
    }
    __syncthreads();
    int p = v - s + (w ? wsum[w-1] : 0);
    if (m0) idx[b*SEQ + p++] = 2*t;
    if (m1) idx[b*SEQ + p]   = 2*t + 1;
    if (t == 1023) cnt[b] = wsum[31];
}

// -------- QKV GEMM with fused input LayerNorm: loads x, LNs tile, streams W ----
__global__ __launch_bounds__(256) void qkv_kernel(const float* __restrict__ X,
        const float* __restrict__ W0, const float* __restrict__ W1,
        const float* __restrict__ W2,
        const float* __restrict__ lnw, const float* __restrict__ lnb,
        float* __restrict__ xn_out,
        __half* __restrict__ O0, __half* __restrict__ O1, __half* __restrict__ O2) {
    extern __shared__ float sm[];
    float* sA = sm;
    float* sW0 = sm + 128 * ASTR;
    float* sW1 = sW0 + 128 * WSTR;
    int tid = threadIdx.x, warp = tid >> 5, lane = tid & 31;
    int g = lane >> 2, tig = lane & 3;
    int rowBase = blockIdx.x * 128;

    const float* Ws[3] = {W0, W1, W2};
    __half* Os[3] = {O0, O1, O2};

    // issue x tile (group), then W0 chunk0 (group) — W0 load overlaps the LN
    for (int i = tid; i < 128 * 32; i += 256) {
        int r = i >> 5, c4 = (i & 31) * 4;
        CPA16(s2u(sA + r * ASTR + c4), &X[(size_t)(rowBase + r) * D + c4], 16);
    }
    CPC();
    for (int i = tid; i < 128 * 8; i += 256) {
        int n = i >> 3, seg = (i & 7) * 4;
        CPA16(s2u(sW0 + n * WSTR + seg), &W0[(size_t)n * D + seg], 16);
    }
    CPC();

    // wait for x (all but newest group complete), then LN tile in smem
    CPW1();
    __syncthreads();
    ln_tile(sA, rowBase, tid, lnw, lnb, xn_out);

    unsigned aBase = s2u(sA) +
        (((warp * 16 + (lane & 7) + ((lane >> 3) & 1) * 8) * ASTR + (lane >> 4) * 4) << 2);
    unsigned wOff =
        ((((lane & 7) + (lane >> 4) * 8) * WSTR + ((lane >> 3) & 1) * 4) << 2);
    unsigned wBase[2] = { s2u(sW0) + wOff, s2u(sW1) + wOff };

    float c[16][4] = {};
    int buf = 0;

    #pragma unroll
    for (int t = 0; t < 12; t++) {
        int wi = t >> 2, kc = t & 3;
        __syncthreads();
        if (t + 1 < 12) {
            const float* Wn = Ws[(t + 1) >> 2];
            int kcn = (t + 1) & 3;
            float* dst = buf ? sW0 : sW1;
            for (int i = tid; i < 128 * 8; i += 256) {
                int n = i >> 3, seg = (i & 7) * 4;
                CPA16(s2u(dst + n * WSTR + seg), &Wn[(size_t)n * D + kcn * 32 + seg], 16);
            }
            CPC();
            CPW1();
        } else {
            CPW0();
        }
        __syncthreads();

        #pragma unroll
        for (int k8 = 0; k8 < 4; k8++) {
            unsigned a[4];
            LDSM_X4(a, aBase + kc * 128 + k8 * 32);
            #pragma unroll
            for (int np = 0; np < 8; np++) {
                unsigned bb[4];
                LDSM_X4(bb, wBase[buf] + np * (16 * WSTR * 4) + k8 * 32);
                MMA_TF32(c[np*2],     a, bb[0], bb[1]);
                MMA_TF32(c[np*2 + 1], a, bb[2], bb[3]);
            }
        }

        if (kc == 3) {
            __half* O = Os[wi];
            int row0 = rowBase + warp * 16 + g;
            bool relu = (wi == 0);
            #pragma unroll
            for (int nt = 0; nt < 16; nt++) {
                int col = nt * 8 + 2 * tig;
                float lx = c[nt][0], ly = c[nt][1], hx = c[nt][2], hy = c[nt][3];
                if (relu) {
                    lx = fmaxf(lx, 0.f); ly = fmaxf(ly, 0.f);
                    hx = fmaxf(hx, 0.f); hy = fmaxf(hy, 0.f);
                }
                *(unsigned*)&O[(size_t)row0 * D + col]       = packh(lx, ly);
                *(unsigned*)&O[(size_t)(row0 + 8) * D + col] = packh(hx, hy);
                c[nt][0] = 0.f; c[nt][1] = 0.f; c[nt][2] = 0.f; c[nt][3] = 0.f;
            }
        }
        buf ^= 1;
    }
}

// -------- fused FFN with input LN: out = sa + relu(LN(sa)@w1^T+b1)@w2^T + b2 ---
__global__ __launch_bounds__(256) void ffn_kernel(const float* __restrict__ SA,
        const float* __restrict__ W1, const float* __restrict__ W2,
        const float* __restrict__ lnw, const float* __restrict__ lnb,
        const float* __restrict__ b1v, const float* __restrict__ b2v,
        float* __restrict__ out) {
    extern __shared__ float sm[];
    float* sA = sm;
    float* sW0 = sm + 128 * ASTR;
    float* sW1 = sW0 + 128 * WSTR;
    int tid = threadIdx.x, warp = tid >> 5, lane = tid & 31;
    int g = lane >> 2, tig = lane & 3;
    int rowBase = blockIdx.x * 128;

    for (int i = tid; i < 128 * 32; i += 256) {
        int r = i >> 5, c4 = (i & 31) * 4;
        CPA16(s2u(sA + r * ASTR + c4), &SA[(size_t)(rowBase + r) * D + c4], 16);
    }
    CPC();
    for (int i = tid; i < 128 * 8; i += 256) {
        int n = i >> 3, seg = (i & 7) * 4;
        CPA16(s2u(sW0 + n * WSTR + seg), &W1[(size_t)n * D + seg], 16);
    }
    CPC();

    // wait for sa tile, LN it in smem (h never touches gmem)
    CPW1();
    __syncthreads();
    ln_tile(sA, rowBase, tid, lnw, lnb, nullptr);

    unsigned aBase = s2u(sA) +
        (((warp * 16 + (lane & 7) + ((lane >> 3) & 1) * 8) * ASTR + (lane >> 4) * 4) << 2);
    unsigned wOff =
        ((((lane & 7) + (lane >> 4) * 8) * WSTR + ((lane >> 3) & 1) * 4) << 2);
    unsigned wBase[2] = { s2u(sW0) + wOff, s2u(sW1) + wOff };

    float c[16][4] = {};
    int buf = 0;

    #pragma unroll
    for (int t = 0; t < 8; t++) {
        int kc = t & 3;
        __syncthreads();
        if (t + 1 < 8) {
            const float* Wn = (t + 1 < 4) ? W1 : W2;
            int kcn = (t + 1) & 3;
            float* dst = buf ? sW0 : sW1;
            for (int i = tid; i < 128 * 8; i += 256) {
                int n = i >> 3, seg = (i & 7) * 4;
                CPA16(s2u(dst + n * WSTR + seg), &Wn[(size_t)n * D + kcn * 32 + seg], 16);
            }
            CPC();
            CPW1();
        } else {
            CPW0();
        }
        __syncthreads();

        #pragma unroll
        for (int k8 = 0; k8 < 4; k8++) {
            unsigned a[4];
            LDSM_X4(a, aBase + kc * 128 + k8 * 32);
            #pragma unroll
            for (int np = 0; np < 8; np++) {
                unsigned bb[4];
                LDSM_X4(bb, wBase[buf] + np * (16 * WSTR * 4) + k8 * 32);
                MMA_TF32(c[np*2],     a, bb[0], bb[1]);
                MMA_TF32(c[np*2 + 1], a, bb[2], bb[3]);
            }
        }

        if (t == 3) {
            __syncthreads();     // everyone done reading phase-1 A (= LN(sa))
            int row0l = warp * 16 + g;
            #pragma unroll
            for (int nt = 0; nt < 16; nt++) {
                int col = nt * 8 + 2 * tig;
                float2 bb = *(const float2*)&b1v[col];
                float2 lo, hi;
                lo.x = __uint_as_float(tf32r(fmaxf(c[nt][0] + bb.x, 0.f)));
                lo.y = __uint_as_float(tf32r(fmaxf(c[nt][1] + bb.y, 0.f)));
                hi.x = __uint_as_float(tf32r(fmaxf(c[nt][2] + bb.x, 0.f)));
                hi.y = __uint_as_float(tf32r(fmaxf(c[nt][3] + bb.y, 0.f)));
                *(float2*)&sA[row0l * ASTR + col] = lo;
                *(float2*)&sA[(row0l + 8) * ASTR + col] = hi;
                c[nt][0] = 0.f; c[nt][1] = 0.f; c[nt][2] = 0.f; c[nt][3] = 0.f;
            }
        }
        if (t == 7) {
            int row0 = rowBase + warp * 16 + g;
            #pragma unroll
            for (int nt = 0; nt < 16; nt++) {
                int col = nt * 8 + 2 * tig;
                float2 bb = *(const float2*)&b2v[col];
                float2 r0v = *(const float2*)&SA[(size_t)row0 * D + col];
                float2 r1v = *(const float2*)&SA[(size_t)(row0 + 8) * D + col];
                float2 lo = make_float2(c[nt][0] + bb.x + r0v.x, c[nt][1] + bb.y + r0v.y);
                float2 hi = make_float2(c[nt][2] + bb.x + r1v.x, c[nt][3] + bb.y + r1v.y);
                *(float2*)&out[(size_t)row0 * D + col] = lo;
                *(float2*)&out[(size_t)(row0 + 8) * D + col] = hi;
            }
        }
        buf ^= 1;
    }
}

// ---------------- fp16 flash attention: 2-stage, max-free, MMA row-sums --------
#define AKS 40
__global__ __launch_bounds__(256) void attn_f16_kernel(
        const __half* __restrict__ gqh, const __half* __restrict__ gkh,
        const __half* __restrict__ gvh, const int* __restrict__ idx,
        const int* __restrict__ cnt, const float* __restrict__ xn,
        float* __restrict__ sa) {
    __shared__ __half sK[2][64][AKS];
    __shared__ __half sV[2][64][AKS];

    int tid = threadIdx.x;
    int warp = tid >> 5, lane = tid & 31;
    int g = lane >> 2, tig = lane & 3;
    int b = blockIdx.y >> 2, h = blockIdx.y & 3;
    int q0 = blockIdx.x * 128 + warp * 16;
    int nb = cnt[b];
    const int* bidx = idx + b * SEQ;

    unsigned onesb = (lane < 4) ? 0x3C003C00u : 0u;

    const float qs = 0.17677669529663687f * 1.4426950408889634f;
    const __half* qp0 = gqh + (size_t)(b * SEQ + q0 + g) * D + h * DK;
    const __half* qp1 = qp0 + 8 * D;
    unsigned qa[2][4];
    #pragma unroll
    for (int ks = 0; ks < 2; ks++) {
        int base = ks * 16 + 2 * tig;
        qa[ks][0] = packh(__half2float(qp0[base]) * qs,     __half2float(qp0[base + 1]) * qs);
        qa[ks][1] = packh(__half2float(qp1[base]) * qs,     __half2float(qp1[base + 1]) * qs);
        qa[ks][2] = packh(__half2float(qp0[base + 8]) * qs, __half2float(qp0[base + 9]) * qs);
        qa[ks][3] = packh(__half2float(qp1[base + 8]) * qs, __half2float(qp1[base + 9]) * qs);
    }

    float o[5][4] = {};          // [0..3]: O d-tiles; [4]: l tile (col 0)

    int fKey = tid >> 2, fSeg = (tid & 3) * 8;
    size_t headOff = (size_t)b * SEQ * D + h * DK + fSeg;

    int kRow = lane & 7, kCol = (lane >> 3) * 8;
    int vKey = ((lane >> 3) & 1) * 8 + (lane & 7);
    int vCol = (lane >> 4) * 8;
    unsigned vB[2] = { s2u(&sV[0][vKey][vCol]), s2u(&sV[1][vKey][vCol]) };

    {
        int p = (fKey < nb) ? 16 : 0;
        int gi = (fKey < nb) ? bidx[fKey] : 0;
        CPA16(s2u(&sK[0][fKey][fSeg]), gkh + headOff + (size_t)gi * D, p);
        CPA16(s2u(&sV[0][fKey][fSeg]), gvh + headOff + (size_t)gi * D, p);
        CPC();
    }

    int buf = 0;
    for (int kb = 0; kb < nb; kb += 64, buf ^= 1) {
        int kv = min(64, nb - kb);
        CPW0();
        __syncthreads();
        if (kb + 64 < nb) {
            int rem = nb - (kb + 64);
            int p = (fKey < rem) ? 16 : 0;
            int gi = (fKey < rem) ? bidx[kb + 64 + fKey] : 0;
            CPA16(s2u(&sK[buf ^ 1][fKey][fSeg]), gkh + headOff + (size_t)gi * D, p);
            CPA16(s2u(&sV[buf ^ 1][fKey][fSeg]), gvh + headOff + (size_t)gi * D, p);
            CPC();
        }

        unsigned kAddr = s2u(&sK[buf][kRow][kCol]);

        // S = Q K^T
        float s[8][4];
        #pragma unroll
        for (int nt = 0; nt < 8; nt++) {
            s[nt][0] = 0.f; s[nt][1] = 0.f; s[nt][2] = 0.f; s[nt][3] = 0.f;
            unsigned kf[4];
            LDSM_X4(kf, kAddr + nt * 8 * AKS * 2);
            MMA_F16(s[nt], qa[0], kf[0], kf[1]);
            MMA_F16(s[nt], qa[1], kf[2], kf[3]);
        }

        if (kv < 64) {
            #pragma unroll
            for (int nt = 0; nt < 8; nt++) {
                int col = nt * 8 + 2 * tig;
                if (col     >= kv) { s[nt][0] = -1000.f; s[nt][2] = -1000.f; }
                if (col + 1 >= kv) { s[nt][1] = -1000.f; s[nt][3] = -1000.f; }
            }
        }

        // P = exp2(S): two scores per MUFU op, pre-packed f16x2
        unsigned p01[8], p23[8];
        #pragma unroll
        for (int nt = 0; nt < 8; nt++) {
            p01[nt] = h2exp2(s[nt][0], s[nt][1]);
            p23[nt] = h2exp2(s[nt][2], s[nt][3]);
        }

        // O += P V ; l += P 1
        #pragma unroll
        for (int ksp = 0; ksp < 4; ksp++) {
            unsigned pa[4] = { p01[2*ksp], p23[2*ksp], p01[2*ksp+1], p23[2*ksp+1] };
            #pragma unroll
            for (int dh = 0; dh < 2; dh++) {
                unsigned vb[4];
                LDSM_X4_T(vb, vB[buf] + (ksp * 16 * AKS + dh * 16) * 2);
                MMA_F16(o[dh*2 + 0], pa, vb[0], vb[1]);
                MMA_F16(o[dh*2 + 1], pa, vb[2], vb[3]);
            }
            MMA_F16(o[4], pa, onesb, onesb);
        }
    }

    // epilogue: sa = xn + O/l
    float l0 = __shfl_sync(0xffffffffu, o[4][0], lane & 28);
    float l1 = __shfl_sync(0xffffffffu, o[4][2], lane & 28);
    float inv0 = (l0 > 0.f) ? 1.f / l0 : 0.f;
    float inv1 = (l1 > 0.f) ? 1.f / l1 : 0.f;
    const float* xp0 = xn + (size_t)(b * SEQ + q0 + g) * D + h * DK;
    const float* xp1 = xp0 + 8 * D;
    float* op0 = sa + (size_t)(b * SEQ + q0 + g) * D + h * DK;
    float* op1 = op0 + 8 * D;
    #pragma unroll
    for (int nt = 0; nt < 4; nt++) {
        int col = nt * 8 + 2 * tig;
        float2 x0 = *(const float2*)(xp0 + col);
        float2 x1 = *(const float2*)(xp1 + col);
        *(float2*)(op0 + col) = make_float2(o[nt][0] * inv0 + x0.x, o[nt][1] * inv0 + x0.y);
        *(float2*)(op1 + col) = make_float2(o[nt][2] * inv1 + x1.x, o[nt][3] * inv1 + x1.y);
    }
}

// ---------------- launch ---------------------------------------------------------
extern "C" void kernel_launch(void* const* d_in, const int* in_sizes, int n_in,
                              void* d_out, int out_size) {
    const float* x    = (const float*)d_in[0];
    const int*   mask = (const int*)  d_in[1];
    const float* ln_w = (const float*)d_in[2];
    const float* ln_b = (const float*)d_in[3];
    const float* wq   = (const float*)d_in[4];
    const float* wk   = (const float*)d_in[5];
    const float* wv   = (const float*)d_in[6];
    const float* w1   = (const float*)d_in[7];
    const float* b1   = (const float*)d_in[8];
    const float* w2   = (const float*)d_in[9];
    const float* b2   = (const float*)d_in[10];
    float* out = (float*)d_out;

    float *xn, *sa, *wr;
    int *cntp, *idxp;
    __half *qh, *kh, *vh;
    cudaGetSymbolAddress((void**)&xn,   g_xn);
    cudaGetSymbolAddress((void**)&sa,   g_sa);
    cudaGetSymbolAddress((void**)&wr,   g_wr);
    cudaGetSymbolAddress((void**)&cntp, g_cnt);
    cudaGetSymbolAddress((void**)&idxp, g_idx);
    cudaGetSymbolAddress((void**)&qh,   g_qh);
    cudaGetSymbolAddress((void**)&kh,   g_kh);
    cudaGetSymbolAddress((void**)&vh,   g_vh);

    cudaFuncSetAttribute(qkv_kernel, cudaFuncAttributeMaxDynamicSharedMemorySize, GEMM_SMEM);
    cudaFuncSetAttribute(ffn_kernel, cudaFuncAttributeMaxDynamicSharedMemorySize, GEMM_SMEM);

    // 0) compact key indices + tf32-round weights
    prep_kernel<<<96, 1024>>>(mask, idxp, cntp, wq, wk, wv, w1, w2, wr);
    // 1) fused LN + QKV: xn = LN(x); q=relu(xn@wq^T), k, v -> fp16
    qkv_kernel<<<ROWS/128, 256, GEMM_SMEM>>>(x, wr, wr + 16384, wr + 32768,
            ln_w, ln_b, xn, qh, kh, vh);
    // 2) attention (writes sa = xn + attn)
    attn_f16_kernel<<<dim3(SEQ/128, BATCH*H), 256>>>(qh, kh, vh, idxp, cntp, xn, sa);
    // 3) fused LN + FFN: out = sa + relu(LN(sa)@w1^T+b1)@w2^T + b2
    ffn_kernel<<<ROWS/128, 256, GEMM_SMEM>>>(sa, wr + 49152, wr + 65536,
            ln_w, ln_b, b1, b2, out);
}

// round 14
// speedup vs baseline: 1.1719x; 1.0969x over previous
#include <cuda_runtime.h>
#include <cuda_bf16.h>
#include <cuda_fp16.h>
#include <math.h>

#define D 128
#define H 4
#define DK 32
#define BATCH 16
#define SEQ 2048
#define ROWS (BATCH*SEQ)   // 32768
#define LNEPS 1e-5f

// ---------------- scratch (static device globals; no allocs allowed) ----------
__device__ float g_xn[ROWS*D];
__device__ float g_sa[ROWS*D];
__device__ __half g_wh[5*D*D];            // fp16 weights (q,k,v,w1,w2)
__device__ int   g_cnt[BATCH];
__device__ int   g_idx[BATCH*SEQ];
__device__ __half g_qh[ROWS*D];           // fp16 Q (relu'd)
__device__ __half g_kh[ROWS*D];           // fp16 K
__device__ __half g_vh[ROWS*D];           // fp16 V

// ---------------- helpers ------------------------------------------------------
__device__ __forceinline__ unsigned packh(float a, float b) {
    __half2 t = __floats2half2_rn(a, b);
    return *(unsigned*)&t;
}
__device__ __forceinline__ unsigned h2exp2(float a, float b) {
    unsigned u = packh(a, b), r;
    asm("ex2.approx.f16x2 %0, %1;" : "=r"(r) : "r"(u));
    return r;
}

#define MMA_F16(c, a, b0, b1) \
    asm volatile("mma.sync.aligned.m16n8k16.row.col.f32.f16.f16.f32 " \
        "{%0,%1,%2,%3}, {%4,%5,%6,%7}, {%8,%9}, {%0,%1,%2,%3};" \
        : "+f"(c[0]), "+f"(c[1]), "+f"(c[2]), "+f"(c[3]) \
        : "r"(a[0]), "r"(a[1]), "r"(a[2]), "r"(a[3]), "r"(b0), "r"(b1))

#define LDSM_X4(r, addr) \
    asm volatile("ldmatrix.sync.aligned.m8n8.x4.shared.b16 {%0,%1,%2,%3}, [%4];" \
        : "=r"(r[0]), "=r"(r[1]), "=r"(r[2]), "=r"(r[3]) : "r"(addr))

#define LDSM_X4_T(r, addr) \
    asm volatile("ldmatrix.sync.aligned.m8n8.x4.trans.shared.b16 {%0,%1,%2,%3}, [%4];" \
        : "=r"(r[0]), "=r"(r[1]), "=r"(r[2]), "=r"(r[3]) : "r"(addr))

#define CPA16(dst, src, pbytes) \
    asm volatile("cp.async.cg.shared.global [%0], [%1], 16, %2;" \
        :: "r"(dst), "l"(src), "r"(pbytes))
#define CPC() asm volatile("cp.async.commit_group;" ::: "memory")
#define CPW0() asm volatile("cp.async.wait_group 0;" ::: "memory")
#define CPW1() asm volatile("cp.async.wait_group 1;" ::: "memory")

__device__ __forceinline__ unsigned s2u(const void* p) {
    return (unsigned)__cvta_generic_to_shared(p);
}

#define AH 136     // fp16 A-tile stride (halves): 272B rows, conflict-free LDSM
#define WH 40      // fp16 W-chunk stride (halves): 80B rows, conflict-free LDSM
#define GEMM_SMEM (128*AH*2 + 2*128*WH*2)    // 55296 B -> 3 CTA/SM

// ---- LayerNorm rows straight from gmem -> fp16 smem tile (+ optional fp32 out)
__device__ __forceinline__ void ln_gmem_f16(const float* __restrict__ X, int rowBase,
        int tid, const float* __restrict__ w, const float* __restrict__ b,
        __half* sAh, float* __restrict__ xn_out) {
    int hw = tid >> 4;          // half-warp id 0..15
    int l  = tid & 15;
    float4 w0 = ((const float4*)w)[l*2], w1 = ((const float4*)w)[l*2+1];
    float4 b0 = ((const float4*)b)[l*2], b1 = ((const float4*)b)[l*2+1];
    #pragma unroll
    for (int it = 0; it < 8; it++) {
        int row = it * 16 + hw;
        const float4* xp = (const float4*)(X + (size_t)(rowBase + row) * D + l * 8);
        float4 v0 = xp[0], v1 = xp[1];
        float s = v0.x+v0.y+v0.z+v0.w + v1.x+v1.y+v1.z+v1.w;
        #pragma unroll
        for (int o = 8; o; o >>= 1) s += __shfl_xor_sync(0xffffffffu, s, o);
        float mu = s * (1.0f / D);
        float d0x=v0.x-mu, d0y=v0.y-mu, d0z=v0.z-mu, d0w=v0.w-mu;
        float d1x=v1.x-mu, d1y=v1.y-mu, d1z=v1.z-mu, d1w=v1.w-mu;
        float ss = d0x*d0x+d0y*d0y+d0z*d0z+d0w*d0w + d1x*d1x+d1y*d1y+d1z*d1z+d1w*d1w;
        #pragma unroll
        for (int o = 8; o; o >>= 1) ss += __shfl_xor_sync(0xffffffffu, ss, o);
        float rstd = rsqrtf(ss * (1.0f / D) + LNEPS);
        float o0x = d0x*rstd*w0.x + b0.x, o0y = d0y*rstd*w0.y + b0.y;
        float o0z = d0z*rstd*w0.z + b0.z, o0w = d0w*rstd*w0.w + b0.w;
        float o1x = d1x*rstd*w1.x + b1.x, o1y = d1y*rstd*w1.y + b1.y;
        float o1z = d1z*rstd*w1.z + b1.z, o1w = d1w*rstd*w1.w + b1.w;
        uint4 u;
        u.x = packh(o0x, o0y); u.y = packh(o0z, o0w);
        u.z = packh(o1x, o1y); u.w = packh(o1z, o1w);
        *(uint4*)&sAh[row * AH + l * 8] = u;
        if (xn_out) {
            float4* op = (float4*)(xn_out + (size_t)(rowBase + row) * D + l * 8);
            op[0] = make_float4(o0x, o0y, o0z, o0w);
            op[1] = make_float4(o1x, o1y, o1z, o1w);
        }
    }
}

// ---------------- prep: mask compaction + fp16-convert all weights -------------
__global__ void prep_kernel(const int* __restrict__ mask,
                            int* __restrict__ idx, int* __restrict__ cnt,
                            const float* __restrict__ wq, const float* __restrict__ wk,
                            const float* __restrict__ wv, const float* __restrict__ w1,
                            const float* __restrict__ w2, __half* __restrict__ wh) {
    __shared__ int wsum[32];
    if (blockIdx.x >= 16) {
        int i = (blockIdx.x - 16) * 1024 + threadIdx.x;
        int which = i >> 14, off = i & 16383;
        const float* srcs[5] = {wq, wk, wv, w1, w2};
        wh[i] = __float2half(srcs[which][off]);
        return;
    }
    int b = blockIdx.x, t = threadIdx.x;
    const int* mb = mask + b * SEQ;
    int m0 = mb[2*t], m1 = mb[2*t+1];
    int s = m0 + m1;
    int lane = t & 31, w = t >> 5;
    int v = s;
    #pragma unroll
    for (int o = 1; o < 32; o <<= 1) {
        int u = __shfl_up_sync(0xffffffffu, v, o);
        if (lane >= o) v += u;
    }
    if (lane == 31) wsum[w] = v;
    __syncthreads();
    if (t < 32) {
        int u = wsum[t];
        #pragma unroll
        for (int o = 1; o < 32; o <<= 1) {
            int x = __shfl_up_sync(0xffffffffu, u, o);
            if (t >= o) u += x;
        }
        wsum[t] = u;
    }
    __syncthreads();
    int p = v - s + (w ? wsum[w-1] : 0);
    if (m0) idx[b*SEQ + p++] = 2*t;
    if (m1) idx[b*SEQ + p]   = 2*t + 1;
    if (t == 1023) cnt[b] = wsum[31];
}

// ---- W chunk streamer: 128 rows x 32 fp16 cols of weight wi, chunk kc ---------
__device__ __forceinline__ void stream_wchunk(__half* dst, const __half* __restrict__ W,
                                              int kc, int tid) {
    #pragma unroll
    for (int j = 0; j < 2; j++) {
        int i = tid + j * 256;
        int n = i >> 2, seg = (i & 3) * 8;     // 8 halves = 16B
        CPA16(s2u(dst + n * WH + seg), &W[(size_t)n * D + kc * 32 + seg], 16);
    }
}

// -------- QKV GEMM (fp16): fused input LN; A resident fp16, W streamed ---------
__global__ __launch_bounds__(256, 3) void qkv_kernel(const float* __restrict__ X,
        const __half* __restrict__ W0, const __half* __restrict__ W1,
        const __half* __restrict__ W2,
        const float* __restrict__ lnw, const float* __restrict__ lnb,
        float* __restrict__ xn_out,
        __half* __restrict__ O0, __half* __restrict__ O1, __half* __restrict__ O2) {
    extern __shared__ __half smh[];
    __half* sA  = smh;                    // 128 x AH
    __half* sW0 = smh + 128 * AH;         // 128 x WH
    __half* sW1 = sW0 + 128 * WH;
    int tid = threadIdx.x, warp = tid >> 5, lane = tid & 31;
    int g = lane >> 2, tig = lane & 3;
    int rowBase = blockIdx.x * 128;

    const __half* Ws[3] = {W0, W1, W2};
    __half* Os[3] = {O0, O1, O2};

    // W0 chunk 0 in flight while we LN the A tile from gmem
    stream_wchunk(sW0, W0, 0, tid);
    CPC();
    ln_gmem_f16(X, rowBase, tid, lnw, lnb, sA, xn_out);
    CPW0();
    __syncthreads();

    unsigned aBase = s2u(sA) +
        (((warp * 16 + (lane & 7) + ((lane >> 3) & 1) * 8) * AH + (lane >> 4) * 8) << 1);
    unsigned wOff = (((lane & 7) * WH + (lane >> 3) * 8) << 1);
    unsigned wBase[2] = { s2u(sW0) + wOff, s2u(sW1) + wOff };

    float c[16][4] = {};
    int buf = 0;

    #pragma unroll
    for (int t = 0; t < 12; t++) {
        int wi = t >> 2, kc = t & 3;
        if (t) __syncthreads();
        if (t + 1 < 12) {
            stream_wchunk(buf ? sW0 : sW1, Ws[(t + 1) >> 2], (t + 1) & 3, tid);
            CPC();
            CPW1();
        } else {
            CPW0();
        }
        __syncthreads();

        unsigned a0[4], a1[4];
        LDSM_X4(a0, aBase + kc * 64);
        LDSM_X4(a1, aBase + kc * 64 + 32);
        #pragma unroll
        for (int nt = 0; nt < 16; nt++) {
            unsigned wb[4];
            LDSM_X4(wb, wBase[buf] + nt * (8 * WH * 2));
            MMA_F16(c[nt], a0, wb[0], wb[1]);
            MMA_F16(c[nt], a1, wb[2], wb[3]);
        }

        if (kc == 3) {
            __half* O = Os[wi];
            int row0 = rowBase + warp * 16 + g;
            bool relu = (wi == 0);
            #pragma unroll
            for (int nt = 0; nt < 16; nt++) {
                int col = nt * 8 + 2 * tig;
                float lx = c[nt][0], ly = c[nt][1], hx = c[nt][2], hy = c[nt][3];
                if (relu) {
                    lx = fmaxf(lx, 0.f); ly = fmaxf(ly, 0.f);
                    hx = fmaxf(hx, 0.f); hy = fmaxf(hy, 0.f);
                }
                *(unsigned*)&O[(size_t)row0 * D + col]       = packh(lx, ly);
                *(unsigned*)&O[(size_t)(row0 + 8) * D + col] = packh(hx, hy);
                c[nt][0] = 0.f; c[nt][1] = 0.f; c[nt][2] = 0.f; c[nt][3] = 0.f;
            }
        }
        buf ^= 1;
    }
}

// -------- FFN (fp16): out = sa + relu(LN(sa)@w1^T+b1)@w2^T + b2 ----------------
__global__ __launch_bounds__(256, 3) void ffn_kernel(const float* __restrict__ SA,
        const __half* __restrict__ W1, const __half* __restrict__ W2,
        const float* __restrict__ lnw, const float* __restrict__ lnb,
        const float* __restrict__ b1v, const float* __restrict__ b2v,
        float* __restrict__ out) {
    extern __shared__ __half smh[];
    __half* sA  = smh;
    __half* sW0 = smh + 128 * AH;
    __half* sW1 = sW0 + 128 * WH;
    int tid = threadIdx.x, warp = tid >> 5, lane = tid & 31;
    int g = lane >> 2, tig = lane & 3;
    int rowBase = blockIdx.x * 128;

    stream_wchunk(sW0, W1, 0, tid);
    CPC();
    ln_gmem_f16(SA, rowBase, tid, lnw, lnb, sA, nullptr);
    CPW0();
    __syncthreads();

    unsigned aBase = s2u(sA) +
        (((warp * 16 + (lane & 7) + ((lane >> 3) & 1) * 8) * AH + (lane >> 4) * 8) << 1);
    unsigned wOff = (((lane & 7) * WH + (lane >> 3) * 8) << 1);
    unsigned wBase[2] = { s2u(sW0) + wOff, s2u(sW1) + wOff };

    float c[16][4] = {};
    int buf = 0;

    #pragma unroll
    for (int t = 0; t < 8; t++) {
        int kc = t & 3;
        if (t) __syncthreads();
        if (t + 1 < 8) {
            stream_wchunk(buf ? sW0 : sW1, (t + 1 < 4) ? W1 : W2, (t + 1) & 3, tid);
            CPC();
            CPW1();
        } else {
            CPW0();
        }
        __syncthreads();

        unsigned a0[4], a1[4];
        LDSM_X4(a0, aBase + kc * 64);
        LDSM_X4(a1, aBase + kc * 64 + 32);
        #pragma unroll
        for (int nt = 0; nt < 16; nt++) {
            unsigned wb[4];
            LDSM_X4(wb, wBase[buf] + nt * (8 * WH * 2));
            MMA_F16(c[nt], a0, wb[0], wb[1]);
            MMA_F16(c[nt], a1, wb[2], wb[3]);
        }

        if (t == 3) {
            // f1 = fp16(relu(c + b1)) overwrites the consumed A tile
            __syncthreads();
            int row0l = warp * 16 + g;
            #pragma unroll
            for (int nt = 0; nt < 16; nt++) {
                int col = nt * 8 + 2 * tig;
                float2 bb = *(const float2*)&b1v[col];
                *(unsigned*)&sA[row0l * AH + col] =
                    packh(fmaxf(c[nt][0] + bb.x, 0.f), fmaxf(c[nt][1] + bb.y, 0.f));
                *(unsigned*)&sA[(row0l + 8) * AH + col] =
                    packh(fmaxf(c[nt][2] + bb.x, 0.f), fmaxf(c[nt][3] + bb.y, 0.f));
                c[nt][0] = 0.f; c[nt][1] = 0.f; c[nt][2] = 0.f; c[nt][3] = 0.f;
            }
        }
        if (t == 7) {
            int row0 = rowBase + warp * 16 + g;
            #pragma unroll
            for (int nt = 0; nt < 16; nt++) {
                int col = nt * 8 + 2 * tig;
                float2 bb = *(const float2*)&b2v[col];
                float2 r0v = *(const float2*)&SA[(size_t)row0 * D + col];
                float2 r1v = *(const float2*)&SA[(size_t)(row0 + 8) * D + col];
                float2 lo = make_float2(c[nt][0] + bb.x + r0v.x, c[nt][1] + bb.y + r0v.y);
                float2 hi = make_float2(c[nt][2] + bb.x + r1v.x, c[nt][3] + bb.y + r1v.y);
                *(float2*)&out[(size_t)row0 * D + col] = lo;
                *(float2*)&out[(size_t)(row0 + 8) * D + col] = hi;
            }
        }
        buf ^= 1;
    }
}

// ---------------- fp16 flash attention: 2-stage, max-free, MMA row-sums --------
#define AKS 40
__global__ __launch_bounds__(256) void attn_f16_kernel(
        const __half* __restrict__ gqh, const __half* __restrict__ gkh,
        const __half* __restrict__ gvh, const int* __restrict__ idx,
        const int* __restrict__ cnt, const float* __restrict__ xn,
        float* __restrict__ sa) {
    __shared__ __half sK[2][64][AKS];
    __shared__ __half sV[2][64][AKS];

    int tid = threadIdx.x;
    int warp = tid >> 5, lane = tid & 31;
    int g = lane >> 2, tig = lane & 3;
    int b = blockIdx.y >> 2, h = blockIdx.y & 3;
    int q0 = blockIdx.x * 128 + warp * 16;
    int nb = cnt[b];
    const int* bidx = idx + b * SEQ;

    unsigned onesb = (lane < 4) ? 0x3C003C00u : 0u;

    const float qs = 0.17677669529663687f * 1.4426950408889634f;
    const __half* qp0 = gqh + (size_t)(b * SEQ + q0 + g) * D + h * DK;
    const __half* qp1 = qp0 + 8 * D;
    unsigned qa[2][4];
    #pragma unroll
    for (int ks = 0; ks < 2; ks++) {
        int base = ks * 16 + 2 * tig;
        qa[ks][0] = packh(__half2float(qp0[base]) * qs,     __half2float(qp0[base + 1]) * qs);
        qa[ks][1] = packh(__half2float(qp1[base]) * qs,     __half2float(qp1[base + 1]) * qs);
        qa[ks][2] = packh(__half2float(qp0[base + 8]) * qs, __half2float(qp0[base + 9]) * qs);
        qa[ks][3] = packh(__half2float(qp1[base + 8]) * qs, __half2float(qp1[base + 9]) * qs);
    }

    float o[5][4] = {};          // [0..3]: O d-tiles; [4]: l tile (col 0)

    int fKey = tid >> 2, fSeg = (tid & 3) * 8;
    size_t headOff = (size_t)b * SEQ * D + h * DK + fSeg;

    int kRow = lane & 7, kCol = (lane >> 3) * 8;
    int vKey = ((lane >> 3) & 1) * 8 + (lane & 7);
    int vCol = (lane >> 4) * 8;
    unsigned vB[2] = { s2u(&sV[0][vKey][vCol]), s2u(&sV[1][vKey][vCol]) };

    {
        int p = (fKey < nb) ? 16 : 0;
        int gi = (fKey < nb) ? bidx[fKey] : 0;
        CPA16(s2u(&sK[0][fKey][fSeg]), gkh + headOff + (size_t)gi * D, p);
        CPA16(s2u(&sV[0][fKey][fSeg]), gvh + headOff + (size_t)gi * D, p);
        CPC();
    }

    int buf = 0;
    for (int kb = 0; kb < nb; kb += 64, buf ^= 1) {
        int kv = min(64, nb - kb);
        CPW0();
        __syncthreads();
        if (kb + 64 < nb) {
            int rem = nb - (kb + 64);
            int p = (fKey < rem) ? 16 : 0;
            int gi = (fKey < rem) ? bidx[kb + 64 + fKey] : 0;
            CPA16(s2u(&sK[buf ^ 1][fKey][fSeg]), gkh + headOff + (size_t)gi * D, p);
            CPA16(s2u(&sV[buf ^ 1][fKey][fSeg]), gvh + headOff + (size_t)gi * D, p);
            CPC();
        }

        unsigned kAddr = s2u(&sK[buf][kRow][kCol]);

        float s[8][4];
        #pragma unroll
        for (int nt = 0; nt < 8; nt++) {
            s[nt][0] = 0.f; s[nt][1] = 0.f; s[nt][2] = 0.f; s[nt][3] = 0.f;
            unsigned kf[4];
            LDSM_X4(kf, kAddr + nt * 8 * AKS * 2);
            MMA_F16(s[nt], qa[0], kf[0], kf[1]);
            MMA_F16(s[nt], qa[1], kf[2], kf[3]);
        }

        if (kv < 64) {
            #pragma unroll
            for (int nt = 0; nt < 8; nt++) {
                int col = nt * 8 + 2 * tig;
                if (col     >= kv) { s[nt][0] = -1000.f; s[nt][2] = -1000.f; }
                if (col + 1 >= kv) { s[nt][1] = -1000.f; s[nt][3] = -1000.f; }
            }
        }

        unsigned p01[8], p23[8];
        #pragma unroll
        for (int nt = 0; nt < 8; nt++) {
            p01[nt] = h2exp2(s[nt][0], s[nt][1]);
            p23[nt] = h2exp2(s[nt][2], s[nt][3]);
        }

        #pragma unroll
        for (int ksp = 0; ksp < 4; ksp++) {
            unsigned pa[4] = { p01[2*ksp], p23[2*ksp], p01[2*ksp+1], p23[2*ksp+1] };
            #pragma unroll
            for (int dh = 0; dh < 2; dh++) {
                unsigned vb[4];
                LDSM_X4_T(vb, vB[buf] + (ksp * 16 * AKS + dh * 16) * 2);
                MMA_F16(o[dh*2 + 0], pa, vb[0], vb[1]);
                MMA_F16(o[dh*2 + 1], pa, vb[2], vb[3]);
            }
            MMA_F16(o[4], pa, onesb, onesb);
        }
    }

    float l0 = __shfl_sync(0xffffffffu, o[4][0], lane & 28);
    float l1 = __shfl_sync(0xffffffffu, o[4][2], lane & 28);
    float inv0 = (l0 > 0.f) ? 1.f / l0 : 0.f;
    float inv1 = (l1 > 0.f) ? 1.f / l1 : 0.f;
    const float* xp0 = xn + (size_t)(b * SEQ + q0 + g) * D + h * DK;
    const float* xp1 = xp0 + 8 * D;
    float* op0 = sa + (size_t)(b * SEQ + q0 + g) * D + h * DK;
    float* op1 = op0 + 8 * D;
    #pragma unroll
    for (int nt = 0; nt < 4; nt++) {
        int col = nt * 8 + 2 * tig;
        float2 x0 = *(const float2*)(xp0 + col);
        float2 x1 = *(const float2*)(xp1 + col);
        *(float2*)(op0 + col) = make_float2(o[nt][0] * inv0 + x0.x, o[nt][1] * inv0 + x0.y);
        *(float2*)(op1 + col) = make_float2(o[nt][2] * inv1 + x1.x, o[nt][3] * inv1 + x1.y);
    }
}

// ---------------- launch ---------------------------------------------------------
extern "C" void kernel_launch(void* const* d_in, const int* in_sizes, int n_in,
                              void* d_out, int out_size) {
    const float* x    = (const float*)d_in[0];
    const int*   mask = (const int*)  d_in[1];
    const float* ln_w = (const float*)d_in[2];
    const float* ln_b = (const float*)d_in[3];
    const float* wq   = (const float*)d_in[4];
    const float* wk   = (const float*)d_in[5];
    const float* wv   = (const float*)d_in[6];
    const float* w1   = (const float*)d_in[7];
    const float* b1   = (const float*)d_in[8];
    const float* w2   = (const float*)d_in[9];
    const float* b2   = (const float*)d_in[10];
    float* out = (float*)d_out;

    float *xn, *sa;
    int *cntp, *idxp;
    __half *wh, *qh, *kh, *vh;
    cudaGetSymbolAddress((void**)&xn,   g_xn);
    cudaGetSymbolAddress((void**)&sa,   g_sa);
    cudaGetSymbolAddress((void**)&wh,   g_wh);
    cudaGetSymbolAddress((void**)&cntp, g_cnt);
    cudaGetSymbolAddress((void**)&idxp, g_idx);
    cudaGetSymbolAddress((void**)&qh,   g_qh);
    cudaGetSymbolAddress((void**)&kh,   g_kh);
    cudaGetSymbolAddress((void**)&vh,   g_vh);

    cudaFuncSetAttribute(qkv_kernel, cudaFuncAttributeMaxDynamicSharedMemorySize, GEMM_SMEM);
    cudaFuncSetAttribute(ffn_kernel, cudaFuncAttributeMaxDynamicSharedMemorySize, GEMM_SMEM);

    // 0) compact key indices + fp16-convert weights
    prep_kernel<<<96, 1024>>>(mask, idxp, cntp, wq, wk, wv, w1, w2, wh);
    // 1) fused LN + QKV (fp16): xn = LN(x); q=relu(xn@wq^T), k, v
    qkv_kernel<<<ROWS/128, 256, GEMM_SMEM>>>(x, wh, wh + 16384, wh + 32768,
            ln_w, ln_b, xn, qh, kh, vh);
    // 2) attention (writes sa = xn + attn)
    attn_f16_kernel<<<dim3(SEQ/128, BATCH*H), 256>>>(qh, kh, vh, idxp, cntp, xn, sa);
    // 3) fused LN + FFN (fp16): out = sa + relu(LN(sa)@w1^T+b1)@w2^T + b2
    ffn_kernel<<<ROWS/128, 256, GEMM_SMEM>>>(sa, wh + 49152, wh + 65536,
            ln_w, ln_b, b1, b2, out);
}

// round 15
// speedup vs baseline: 1.1869x; 1.0129x over previous
#include <cuda_runtime.h>
#include <cuda_bf16.h>
#include <cuda_fp16.h>
#include <math.h>

#define D 128
#define H 4
#define DK 32
#define BATCH 16
#define SEQ 2048
#define ROWS (BATCH*SEQ)   // 32768
#define LNEPS 1e-5f

// ---------------- scratch (static device globals; no allocs allowed) ----------
__device__ float g_xn[ROWS*D];
__device__ float g_sa[ROWS*D];
__device__ __half g_wh[5*D*D];            // fp16 weights (q,k,v,w1,w2)
__device__ int   g_cnt[BATCH];
__device__ int   g_idx[BATCH*SEQ];
__device__ __half g_qh[ROWS*D];           // fp16 Q (relu'd)
__device__ __half g_kh[ROWS*D];           // fp16 K
__device__ __half g_vh[ROWS*D];           // fp16 V

// ---------------- helpers ------------------------------------------------------
__device__ __forceinline__ unsigned packh(float a, float b) {
    __half2 t = __floats2half2_rn(a, b);
    return *(unsigned*)&t;
}
__device__ __forceinline__ unsigned h2exp2(float a, float b) {
    unsigned u = packh(a, b), r;
    asm("ex2.approx.f16x2 %0, %1;" : "=r"(r) : "r"(u));
    return r;
}

#define MMA_F16(c, a, b0, b1) \
    asm volatile("mma.sync.aligned.m16n8k16.row.col.f32.f16.f16.f32 " \
        "{%0,%1,%2,%3}, {%4,%5,%6,%7}, {%8,%9}, {%0,%1,%2,%3};" \
        : "+f"(c[0]), "+f"(c[1]), "+f"(c[2]), "+f"(c[3]) \
        : "r"(a[0]), "r"(a[1]), "r"(a[2]), "r"(a[3]), "r"(b0), "r"(b1))

#define LDSM_X4(r, addr) \
    asm volatile("ldmatrix.sync.aligned.m8n8.x4.shared.b16 {%0,%1,%2,%3}, [%4];" \
        : "=r"(r[0]), "=r"(r[1]), "=r"(r[2]), "=r"(r[3]) : "r"(addr))

#define LDSM_X4_T(r, addr) \
    asm volatile("ldmatrix.sync.aligned.m8n8.x4.trans.shared.b16 {%0,%1,%2,%3}, [%4];" \
        : "=r"(r[0]), "=r"(r[1]), "=r"(r[2]), "=r"(r[3]) : "r"(addr))

#define CPA16(dst, src, pbytes) \
    asm volatile("cp.async.cg.shared.global [%0], [%1], 16, %2;" \
        :: "r"(dst), "l"(src), "r"(pbytes))
#define CPC() asm volatile("cp.async.commit_group;" ::: "memory")
#define CPW0() asm volatile("cp.async.wait_group 0;" ::: "memory")
#define CPW1() asm volatile("cp.async.wait_group 1;" ::: "memory")

__device__ __forceinline__ unsigned s2u(const void* p) {
    return (unsigned)__cvta_generic_to_shared(p);
}

#define AH 136     // fp16 A-tile stride (halves)
#define WH 40      // fp16 W-chunk stride (halves)
#define MT 64      // GEMM M-tile rows
#define GEMM_SMEM (MT*AH*2 + 2*128*WH*2)    // 37888 B -> 4+ CTA/SM

// ---- LayerNorm rows straight from gmem -> fp16 smem tile (+ optional fp32 out)
__device__ __forceinline__ void ln_gmem_f16(const float* __restrict__ X, int rowBase,
        int tid, const float* __restrict__ w, const float* __restrict__ b,
        __half* sAh, float* __restrict__ xn_out) {
    int hw = tid >> 4;          // half-warp id 0..15
    int l  = tid & 15;
    float4 w0 = ((const float4*)w)[l*2], w1 = ((const float4*)w)[l*2+1];
    float4 b0 = ((const float4*)b)[l*2], b1 = ((const float4*)b)[l*2+1];
    #pragma unroll
    for (int it = 0; it < MT/16; it++) {
        int row = it * 16 + hw;
        const float4* xp = (const float4*)(X + (size_t)(rowBase + row) * D + l * 8);
        float4 v0 = xp[0], v1 = xp[1];
        float s = v0.x+v0.y+v0.z+v0.w + v1.x+v1.y+v1.z+v1.w;
        #pragma unroll
        for (int o = 8; o; o >>= 1) s += __shfl_xor_sync(0xffffffffu, s, o);
        float mu = s * (1.0f / D);
        float d0x=v0.x-mu, d0y=v0.y-mu, d0z=v0.z-mu, d0w=v0.w-mu;
        float d1x=v1.x-mu, d1y=v1.y-mu, d1z=v1.z-mu, d1w=v1.w-mu;
        float ss = d0x*d0x+d0y*d0y+d0z*d0z+d0w*d0w + d1x*d1x+d1y*d1y+d1z*d1z+d1w*d1w;
        #pragma unroll
        for (int o = 8; o; o >>= 1) ss += __shfl_xor_sync(0xffffffffu, ss, o);
        float rstd = rsqrtf(ss * (1.0f / D) + LNEPS);
        float o0x = d0x*rstd*w0.x + b0.x, o0y = d0y*rstd*w0.y + b0.y;
        float o0z = d0z*rstd*w0.z + b0.z, o0w = d0w*rstd*w0.w + b0.w;
        float o1x = d1x*rstd*w1.x + b1.x, o1y = d1y*rstd*w1.y + b1.y;
        float o1z = d1z*rstd*w1.z + b1.z, o1w = d1w*rstd*w1.w + b1.w;
        uint4 u;
        u.x = packh(o0x, o0y); u.y = packh(o0z, o0w);
        u.z = packh(o1x, o1y); u.w = packh(o1z, o1w);
        *(uint4*)&sAh[row * AH + l * 8] = u;
        if (xn_out) {
            float4* op = (float4*)(xn_out + (size_t)(rowBase + row) * D + l * 8);
            op[0] = make_float4(o0x, o0y, o0z, o0w);
            op[1] = make_float4(o1x, o1y, o1z, o1w);
        }
    }
}

// ---------------- prep: mask compaction + fp16-convert all weights -------------
__global__ void prep_kernel(const int* __restrict__ mask,
                            int* __restrict__ idx, int* __restrict__ cnt,
                            const float* __restrict__ wq, const float* __restrict__ wk,
                            const float* __restrict__ wv, const float* __restrict__ w1,
                            const float* __restrict__ w2, __half* __restrict__ wh) {
    __shared__ int wsum[32];
    if (blockIdx.x >= 16) {
        int i = (blockIdx.x - 16) * 1024 + threadIdx.x;
        int which = i >> 14, off = i & 16383;
        const float* srcs[5] = {wq, wk, wv, w1, w2};
        wh[i] = __float2half(srcs[which][off]);
        return;
    }
    int b = blockIdx.x, t = threadIdx.x;
    const int* mb = mask + b * SEQ;
    int m0 = mb[2*t], m1 = mb[2*t+1];
    int s = m0 + m1;
    int lane = t & 31, w = t >> 5;
    int v = s;
    #pragma unroll
    for (int o = 1; o < 32; o <<= 1) {
        int u = __shfl_up_sync(0xffffffffu, v, o);
        if (lane >= o) v += u;
    }
    if (lane == 31) wsum[w] = v;
    __syncthreads();
    if (t < 32) {
        int u = wsum[t];
        #pragma unroll
        for (int o = 1; o < 32; o <<= 1) {
            int x = __shfl_up_sync(0xffffffffu, u, o);
            if (t >= o) u += x;
        }
        wsum[t] = u;
    }
    __syncthreads();
    int p = v - s + (w ? wsum[w-1] : 0);
    if (m0) idx[b*SEQ + p++] = 2*t;
    if (m1) idx[b*SEQ + p]   = 2*t + 1;
    if (t == 1023) cnt[b] = wsum[31];
}

// ---- W chunk streamer: 128 rows x 32 fp16 cols of weight wi, chunk kc ---------
__device__ __forceinline__ void stream_wchunk(__half* dst, const __half* __restrict__ W,
                                              int kc, int tid) {
    #pragma unroll
    for (int j = 0; j < 2; j++) {
        int i = tid + j * 256;
        int n = i >> 2, seg = (i & 3) * 8;
        CPA16(s2u(dst + n * WH + seg), &W[(size_t)n * D + kc * 32 + seg], 16);
    }
}

// -------- QKV GEMM (fp16, M=64 tiles): fused LN; warp = rowQuad x nHalf --------
__global__ __launch_bounds__(256, 4) void qkv_kernel(const float* __restrict__ X,
        const __half* __restrict__ W0, const __half* __restrict__ W1,
        const __half* __restrict__ W2,
        const float* __restrict__ lnw, const float* __restrict__ lnb,
        float* __restrict__ xn_out,
        __half* __restrict__ O0, __half* __restrict__ O1, __half* __restrict__ O2) {
    extern __shared__ __half smh[];
    __half* sA  = smh;                    // MT x AH
    __half* sW0 = smh + MT * AH;          // 128 x WH
    __half* sW1 = sW0 + 128 * WH;
    int tid = threadIdx.x, warp = tid >> 5, lane = tid & 31;
    int rq = warp >> 1, nh = warp & 1;
    int g = lane >> 2, tig = lane & 3;
    int rowBase = blockIdx.x * MT;

    const __half* Ws[3] = {W0, W1, W2};
    __half* Os[3] = {O0, O1, O2};

    stream_wchunk(sW0, W0, 0, tid);
    CPC();
    ln_gmem_f16(X, rowBase, tid, lnw, lnb, sA, xn_out);
    CPW0();
    __syncthreads();

    unsigned aBase = s2u(sA) +
        (((rq * 16 + (lane & 7) + ((lane >> 3) & 1) * 8) * AH + (lane >> 4) * 8) << 1);
    unsigned wOff = ((((lane & 7) + nh * 64) * WH + (lane >> 3) * 8) << 1);
    unsigned wBase[2] = { s2u(sW0) + wOff, s2u(sW1) + wOff };

    float c[8][4] = {};
    int buf = 0;

    #pragma unroll
    for (int t = 0; t < 12; t++) {
        int wi = t >> 2, kc = t & 3;
        if (t) __syncthreads();
        if (t + 1 < 12) {
            stream_wchunk(buf ? sW0 : sW1, Ws[(t + 1) >> 2], (t + 1) & 3, tid);
            CPC();
            CPW1();
        } else {
            CPW0();
        }
        __syncthreads();

        unsigned a0[4], a1[4];
        LDSM_X4(a0, aBase + kc * 64);
        LDSM_X4(a1, aBase + kc * 64 + 32);
        #pragma unroll
        for (int nt = 0; nt < 8; nt++) {
            unsigned wb[4];
            LDSM_X4(wb, wBase[buf] + nt * (8 * WH * 2));
            MMA_F16(c[nt], a0, wb[0], wb[1]);
            MMA_F16(c[nt], a1, wb[2], wb[3]);
        }

        if (kc == 3) {
            __half* O = Os[wi];
            int row0 = rowBase + rq * 16 + g;
            bool relu = (wi == 0);
            #pragma unroll
            for (int nt = 0; nt < 8; nt++) {
                int col = nh * 64 + nt * 8 + 2 * tig;
                float lx = c[nt][0], ly = c[nt][1], hx = c[nt][2], hy = c[nt][3];
                if (relu) {
                    lx = fmaxf(lx, 0.f); ly = fmaxf(ly, 0.f);
                    hx = fmaxf(hx, 0.f); hy = fmaxf(hy, 0.f);
                }
                *(unsigned*)&O[(size_t)row0 * D + col]       = packh(lx, ly);
                *(unsigned*)&O[(size_t)(row0 + 8) * D + col] = packh(hx, hy);
                c[nt][0] = 0.f; c[nt][1] = 0.f; c[nt][2] = 0.f; c[nt][3] = 0.f;
            }
        }
        buf ^= 1;
    }
}

// -------- FFN (fp16, M=64): out = sa + relu(LN(sa)@w1^T+b1)@w2^T + b2 ----------
__global__ __launch_bounds__(256, 4) void ffn_kernel(const float* __restrict__ SA,
        const __half* __restrict__ W1, const __half* __restrict__ W2,
        const float* __restrict__ lnw, const float* __restrict__ lnb,
        const float* __restrict__ b1v, const float* __restrict__ b2v,
        float* __restrict__ out) {
    extern __shared__ __half smh[];
    __half* sA  = smh;
    __half* sW0 = smh + MT * AH;
    __half* sW1 = sW0 + 128 * WH;
    int tid = threadIdx.x, warp = tid >> 5, lane = tid & 31;
    int rq = warp >> 1, nh = warp & 1;
    int g = lane >> 2, tig = lane & 3;
    int rowBase = blockIdx.x * MT;

    stream_wchunk(sW0, W1, 0, tid);
    CPC();
    ln_gmem_f16(SA, rowBase, tid, lnw, lnb, sA, nullptr);
    CPW0();
    __syncthreads();

    unsigned aBase = s2u(sA) +
        (((rq * 16 + (lane & 7) + ((lane >> 3) & 1) * 8) * AH + (lane >> 4) * 8) << 1);
    unsigned wOff = ((((lane & 7) + nh * 64) * WH + (lane >> 3) * 8) << 1);
    unsigned wBase[2] = { s2u(sW0) + wOff, s2u(sW1) + wOff };

    float c[8][4] = {};
    int buf = 0;

    #pragma unroll
    for (int t = 0; t < 8; t++) {
        int kc = t & 3;
        if (t) __syncthreads();
        if (t + 1 < 8) {
            stream_wchunk(buf ? sW0 : sW1, (t + 1 < 4) ? W1 : W2, (t + 1) & 3, tid);
            CPC();
            CPW1();
        } else {
            CPW0();
        }
        __syncthreads();

        unsigned a0[4], a1[4];
        LDSM_X4(a0, aBase + kc * 64);
        LDSM_X4(a1, aBase + kc * 64 + 32);
        #pragma unroll
        for (int nt = 0; nt < 8; nt++) {
            unsigned wb[4];
            LDSM_X4(wb, wBase[buf] + nt * (8 * WH * 2));
            MMA_F16(c[nt], a0, wb[0], wb[1]);
            MMA_F16(c[nt], a1, wb[2], wb[3]);
        }

        if (t == 3) {
            // f1 = fp16(relu(c + b1)) overwrites consumed A tile (64x128 covered
            // by 8 warps: rows rq*16..+16, cols nh*64..+64)
            __syncthreads();
            int row0l = rq * 16 + g;
            #pragma unroll
            for (int nt = 0; nt < 8; nt++) {
                int col = nh * 64 + nt * 8 + 2 * tig;
                float2 bb = *(const float2*)&b1v[col];
                *(unsigned*)&sA[row0l * AH + col] =
                    packh(fmaxf(c[nt][0] + bb.x, 0.f), fmaxf(c[nt][1] + bb.y, 0.f));
                *(unsigned*)&sA[(row0l + 8) * AH + col] =
                    packh(fmaxf(c[nt][2] + bb.x, 0.f), fmaxf(c[nt][3] + bb.y, 0.f));
                c[nt][0] = 0.f; c[nt][1] = 0.f; c[nt][2] = 0.f; c[nt][3] = 0.f;
            }
        }
        if (t == 7) {
            int row0 = rowBase + rq * 16 + g;
            #pragma unroll
            for (int nt = 0; nt < 8; nt++) {
                int col = nh * 64 + nt * 8 + 2 * tig;
                float2 bb = *(const float2*)&b2v[col];
                float2 r0v = *(const float2*)&SA[(size_t)row0 * D + col];
                float2 r1v = *(const float2*)&SA[(size_t)(row0 + 8) * D + col];
                float2 lo = make_float2(c[nt][0] + bb.x + r0v.x, c[nt][1] + bb.y + r0v.y);
                float2 hi = make_float2(c[nt][2] + bb.x + r1v.x, c[nt][3] + bb.y + r1v.y);
                *(float2*)&out[(size_t)row0 * D + col] = lo;
                *(float2*)&out[(size_t)(row0 + 8) * D + col] = hi;
            }
        }
        buf ^= 1;
    }
}

// ---------------- fp16 flash attention: reg-diet, 4 CTA/SM ---------------------
// exp fused into the S loop (no s[8][4] live array) -> ~64 regs ->
// __launch_bounds__(256,4): 592 CTA slots, 1024 CTAs = 2 flat waves.
#define AKS 40
__global__ __launch_bounds__(256, 4) void attn_f16_kernel(
        const __half* __restrict__ gqh, const __half* __restrict__ gkh,
        const __half* __restrict__ gvh, const int* __restrict__ idx,
        const int* __restrict__ cnt, const float* __restrict__ xn,
        float* __restrict__ sa) {
    __shared__ __half sK[2][64][AKS];
    __shared__ __half sV[2][64][AKS];

    int tid = threadIdx.x;
    int warp = tid >> 5, lane = tid & 31;
    int g = lane >> 2, tig = lane & 3;
    int b = blockIdx.y >> 2, h = blockIdx.y & 3;
    int q0 = blockIdx.x * 128 + warp * 16;
    int nb = cnt[b];
    const int* bidx = idx + b * SEQ;

    unsigned onesb = (lane < 4) ? 0x3C003C00u : 0u;

    const float qs = 0.17677669529663687f * 1.4426950408889634f;
    const __half* qp0 = gqh + (size_t)(b * SEQ + q0 + g) * D + h * DK;
    const __half* qp1 = qp0 + 8 * D;
    unsigned qa[2][4];
    #pragma unroll
    for (int ks = 0; ks < 2; ks++) {
        int base = ks * 16 + 2 * tig;
        qa[ks][0] = packh(__half2float(qp0[base]) * qs,     __half2float(qp0[base + 1]) * qs);
        qa[ks][1] = packh(__half2float(qp1[base]) * qs,     __half2float(qp1[base + 1]) * qs);
        qa[ks][2] = packh(__half2float(qp0[base + 8]) * qs, __half2float(qp0[base + 9]) * qs);
        qa[ks][3] = packh(__half2float(qp1[base + 8]) * qs, __half2float(qp1[base + 9]) * qs);
    }

    float o[5][4] = {};          // [0..3]: O d-tiles; [4]: l tile (col 0)

    int fKey = tid >> 2, fSeg = (tid & 3) * 8;
    size_t headOff = (size_t)b * SEQ * D + h * DK + fSeg;

    int kRow = lane & 7, kCol = (lane >> 3) * 8;
    int vKey = ((lane >> 3) & 1) * 8 + (lane & 7);
    int vCol = (lane >> 4) * 8;
    unsigned vB[2] = { s2u(&sV[0][vKey][vCol]), s2u(&sV[1][vKey][vCol]) };

    {
        int p = (fKey < nb) ? 16 : 0;
        int gi = (fKey < nb) ? bidx[fKey] : 0;
        CPA16(s2u(&sK[0][fKey][fSeg]), gkh + headOff + (size_t)gi * D, p);
        CPA16(s2u(&sV[0][fKey][fSeg]), gvh + headOff + (size_t)gi * D, p);
        CPC();
    }

    int buf = 0;
    for (int kb = 0; kb < nb; kb += 64, buf ^= 1) {
        int kv = min(64, nb - kb);
        CPW0();
        __syncthreads();
        if (kb + 64 < nb) {
            int rem = nb - (kb + 64);
            int p = (fKey < rem) ? 16 : 0;
            int gi = (fKey < rem) ? bidx[kb + 64 + fKey] : 0;
            CPA16(s2u(&sK[buf ^ 1][fKey][fSeg]), gkh + headOff + (size_t)gi * D, p);
            CPA16(s2u(&sV[buf ^ 1][fKey][fSeg]), gvh + headOff + (size_t)gi * D, p);
            CPC();
        }

        unsigned kAddr = s2u(&sK[buf][kRow][kCol]);

        // S = Q K^T with exp fused per n-tile (no live s array)
        unsigned p01[8], p23[8];
        #pragma unroll
        for (int nt = 0; nt < 8; nt++) {
            float s4[4] = {0.f, 0.f, 0.f, 0.f};
            unsigned kf[4];
            LDSM_X4(kf, kAddr + nt * 8 * AKS * 2);
            MMA_F16(s4, qa[0], kf[0], kf[1]);
            MMA_F16(s4, qa[1], kf[2], kf[3]);
            if (kv < 64) {
                int col = nt * 8 + 2 * tig;
                if (col     >= kv) { s4[0] = -1000.f; s4[2] = -1000.f; }
                if (col + 1 >= kv) { s4[1] = -1000.f; s4[3] = -1000.f; }
            }
            p01[nt] = h2exp2(s4[0], s4[1]);
            p23[nt] = h2exp2(s4[2], s4[3]);
        }

        // O += P V ; l += P 1
        #pragma unroll
        for (int ksp = 0; ksp < 4; ksp++) {
            unsigned pa[4] = { p01[2*ksp], p23[2*ksp], p01[2*ksp+1], p23[2*ksp+1] };
            #pragma unroll
            for (int dh = 0; dh < 2; dh++) {
                unsigned vb[4];
                LDSM_X4_T(vb, vB[buf] + (ksp * 16 * AKS + dh * 16) * 2);
                MMA_F16(o[dh*2 + 0], pa, vb[0], vb[1]);
                MMA_F16(o[dh*2 + 1], pa, vb[2], vb[3]);
            }
            MMA_F16(o[4], pa, onesb, onesb);
        }
    }

    // epilogue: sa = xn + O/l
    float l0 = __shfl_sync(0xffffffffu, o[4][0], lane & 28);
    float l1 = __shfl_sync(0xffffffffu, o[4][2], lane & 28);
    float inv0 = (l0 > 0.f) ? 1.f / l0 : 0.f;
    float inv1 = (l1 > 0.f) ? 1.f / l1 : 0.f;
    const float* xp0 = xn + (size_t)(b * SEQ + q0 + g) * D + h * DK;
    const float* xp1 = xp0 + 8 * D;
    float* op0 = sa + (size_t)(b * SEQ + q0 + g) * D + h * DK;
    float* op1 = op0 + 8 * D;
    #pragma unroll
    for (int nt = 0; nt < 4; nt++) {
        int col = nt * 8 + 2 * tig;
        float2 x0 = *(const float2*)(xp0 + col);
        float2 x1 = *(const float2*)(xp1 + col);
        *(float2*)(op0 + col) = make_float2(o[nt][0] * inv0 + x0.x, o[nt][1] * inv0 + x0.y);
        *(float2*)(op1 + col) = make_float2(o[nt][2] * inv1 + x1.x, o[nt][3] * inv1 + x1.y);
    }
}

// ---------------- launch ---------------------------------------------------------
extern "C" void kernel_launch(void* const* d_in, const int* in_sizes, int n_in,
                              void* d_out, int out_size) {
    const float* x    = (const float*)d_in[0];
    const int*   mask = (const int*)  d_in[1];
    const float* ln_w = (const float*)d_in[2];
    const float* ln_b = (const float*)d_in[3];
    const float* wq   = (const float*)d_in[4];
    const float* wk   = (const float*)d_in[5];
    const float* wv   = (const float*)d_in[6];
    const float* w1   = (const float*)d_in[7];
    const float* b1   = (const float*)d_in[8];
    const float* w2   = (const float*)d_in[9];
    const float* b2   = (const float*)d_in[10];
    float* out = (float*)d_out;

    float *xn, *sa;
    int *cntp, *idxp;
    __half *wh, *qh, *kh, *vh;
    cudaGetSymbolAddress((void**)&xn,   g_xn);
    cudaGetSymbolAddress((void**)&sa,   g_sa);
    cudaGetSymbolAddress((void**)&wh,   g_wh);
    cudaGetSymbolAddress((void**)&cntp, g_cnt);
    cudaGetSymbolAddress((void**)&idxp, g_idx);
    cudaGetSymbolAddress((void**)&qh,   g_qh);
    cudaGetSymbolAddress((void**)&kh,   g_kh);
    cudaGetSymbolAddress((void**)&vh,   g_vh);

    cudaFuncSetAttribute(qkv_kernel, cudaFuncAttributeMaxDynamicSharedMemorySize, GEMM_SMEM);
    cudaFuncSetAttribute(ffn_kernel, cudaFuncAttributeMaxDynamicSharedMemorySize, GEMM_SMEM);

    // 0) compact key indices + fp16-convert weights
    prep_kernel<<<96, 1024>>>(mask, idxp, cntp, wq, wk, wv, w1, w2, wh);
    // 1) fused LN + QKV (fp16, M=64): xn = LN(x); q=relu(xn@wq^T), k, v
    qkv_kernel<<<ROWS/MT, 256, GEMM_SMEM>>>(x, wh, wh + 16384, wh + 32768,
            ln_w, ln_b, xn, qh, kh, vh);
    // 2) attention (writes sa = xn + attn)
    attn_f16_kernel<<<dim3(SEQ/128, BATCH*H), 256>>>(qh, kh, vh, idxp, cntp, xn, sa);
    // 3) fused LN + FFN (fp16, M=64): out = sa + relu(LN(sa)@w1^T+b1)@w2^T + b2
    ffn_kernel<<<ROWS/MT, 256, GEMM_SMEM>>>(sa, wh + 49152, wh + 65536,
            ln_w, ln_b, b1, b2, out);
}

// round 16
// speedup vs baseline: 1.1905x; 1.0030x over previous
#include <cuda_runtime.h>
#include <cuda_bf16.h>
#include <cuda_fp16.h>
#include <math.h>

#define D 128
#define H 4
#define DK 32
#define BATCH 16
#define SEQ 2048
#define ROWS (BATCH*SEQ)   // 32768
#define LNEPS 1e-5f

// ---------------- scratch (static device globals; no allocs allowed) ----------
__device__ float g_xn[ROWS*D];
__device__ float g_sa[ROWS*D];
__device__ __half g_wh[5*D*D];            // fp16 weights (q,k,v,w1,w2)
__device__ int   g_cnt[BATCH];
__device__ int   g_idx[BATCH*SEQ];
__device__ __half g_qh[ROWS*D];           // fp16 Q (relu'd)
__device__ __half g_kh[ROWS*D];           // fp16 K
__device__ __half g_vh[ROWS*D];           // fp16 V

// ---------------- helpers ------------------------------------------------------
__device__ __forceinline__ unsigned packh(float a, float b) {
    __half2 t = __floats2half2_rn(a, b);
    return *(unsigned*)&t;
}
__device__ __forceinline__ unsigned h2exp2(float a, float b) {
    unsigned u = packh(a, b), r;
    asm("ex2.approx.f16x2 %0, %1;" : "=r"(r) : "r"(u));
    return r;
}

#define MMA_F16(c, a, b0, b1) \
    asm volatile("mma.sync.aligned.m16n8k16.row.col.f32.f16.f16.f32 " \
        "{%0,%1,%2,%3}, {%4,%5,%6,%7}, {%8,%9}, {%0,%1,%2,%3};" \
        : "+f"(c[0]), "+f"(c[1]), "+f"(c[2]), "+f"(c[3]) \
        : "r"(a[0]), "r"(a[1]), "r"(a[2]), "r"(a[3]), "r"(b0), "r"(b1))

#define LDSM_X4(r, addr) \
    asm volatile("ldmatrix.sync.aligned.m8n8.x4.shared.b16 {%0,%1,%2,%3}, [%4];" \
        : "=r"(r[0]), "=r"(r[1]), "=r"(r[2]), "=r"(r[3]) : "r"(addr))

#define LDSM_X4_T(r, addr) \
    asm volatile("ldmatrix.sync.aligned.m8n8.x4.trans.shared.b16 {%0,%1,%2,%3}, [%4];" \
        : "=r"(r[0]), "=r"(r[1]), "=r"(r[2]), "=r"(r[3]) : "r"(addr))

#define CPA16(dst, src, pbytes) \
    asm volatile("cp.async.cg.shared.global [%0], [%1], 16, %2;" \
        :: "r"(dst), "l"(src), "r"(pbytes))
#define CPC() asm volatile("cp.async.commit_group;" ::: "memory")
#define CPW0() asm volatile("cp.async.wait_group 0;" ::: "memory")
#define CPW1() asm volatile("cp.async.wait_group 1;" ::: "memory")

__device__ __forceinline__ unsigned s2u(const void* p) {
    return (unsigned)__cvta_generic_to_shared(p);
}

#define AH 136     // fp16 A-tile stride (halves)
#define WH 72      // fp16 W-chunk stride (halves): 144B rows, conflict-free LDSM
#define MT 64      // GEMM M-tile rows
#define GEMM_SMEM (MT*AH*2 + 2*128*WH*2)    // 54272 B -> 4 CTA/SM

// ---- LayerNorm rows straight from gmem -> fp16 smem tile (+ optional fp32 out)
__device__ __forceinline__ void ln_gmem_f16(const float* __restrict__ X, int rowBase,
        int tid, const float* __restrict__ w, const float* __restrict__ b,
        __half* sAh, float* __restrict__ xn_out) {
    int hw = tid >> 4;          // half-warp id 0..15
    int l  = tid & 15;
    float4 w0 = ((const float4*)w)[l*2], w1 = ((const float4*)w)[l*2+1];
    float4 b0 = ((const float4*)b)[l*2], b1 = ((const float4*)b)[l*2+1];
    #pragma unroll
    for (int it = 0; it < MT/16; it++) {
        int row = it * 16 + hw;
        const float4* xp = (const float4*)(X + (size_t)(rowBase + row) * D + l * 8);
        float4 v0 = xp[0], v1 = xp[1];
        float s = v0.x+v0.y+v0.z+v0.w + v1.x+v1.y+v1.z+v1.w;
        #pragma unroll
        for (int o = 8; o; o >>= 1) s += __shfl_xor_sync(0xffffffffu, s, o);
        float mu = s * (1.0f / D);
        float d0x=v0.x-mu, d0y=v0.y-mu, d0z=v0.z-mu, d0w=v0.w-mu;
        float d1x=v1.x-mu, d1y=v1.y-mu, d1z=v1.z-mu, d1w=v1.w-mu;
        float ss = d0x*d0x+d0y*d0y+d0z*d0z+d0w*d0w + d1x*d1x+d1y*d1y+d1z*d1z+d1w*d1w;
        #pragma unroll
        for (int o = 8; o; o >>= 1) ss += __shfl_xor_sync(0xffffffffu, ss, o);
        float rstd = rsqrtf(ss * (1.0f / D) + LNEPS);
        float o0x = d0x*rstd*w0.x + b0.x, o0y = d0y*rstd*w0.y + b0.y;
        float o0z = d0z*rstd*w0.z + b0.z, o0w = d0w*rstd*w0.w + b0.w;
        float o1x = d1x*rstd*w1.x + b1.x, o1y = d1y*rstd*w1.y + b1.y;
        float o1z = d1z*rstd*w1.z + b1.z, o1w = d1w*rstd*w1.w + b1.w;
        uint4 u;
        u.x = packh(o0x, o0y); u.y = packh(o0z, o0w);
        u.z = packh(o1x, o1y); u.w = packh(o1z, o1w);
        *(uint4*)&sAh[row * AH + l * 8] = u;
        if (xn_out) {
            float4* op = (float4*)(xn_out + (size_t)(rowBase + row) * D + l * 8);
            op[0] = make_float4(o0x, o0y, o0z, o0w);
            op[1] = make_float4(o1x, o1y, o1z, o1w);
        }
    }
}

// ---------------- prep: mask compaction + fp16-convert all weights -------------
__global__ void prep_kernel(const int* __restrict__ mask,
                            int* __restrict__ idx, int* __restrict__ cnt,
                            const float* __restrict__ wq, const float* __restrict__ wk,
                            const float* __restrict__ wv, const float* __restrict__ w1,
                            const float* __restrict__ w2, __half* __restrict__ wh) {
    __shared__ int wsum[32];
    if (blockIdx.x >= 16) {
        int i = (blockIdx.x - 16) * 1024 + threadIdx.x;
        int which = i >> 14, off = i & 16383;
        const float* srcs[5] = {wq, wk, wv, w1, w2};
        wh[i] = __float2half(srcs[which][off]);
        return;
    }
    int b = blockIdx.x, t = threadIdx.x;
    const int* mb = mask + b * SEQ;
    int m0 = mb[2*t], m1 = mb[2*t+1];
    int s = m0 + m1;
    int lane = t & 31, w = t >> 5;
    int v = s;
    #pragma unroll
    for (int o = 1; o < 32; o <<= 1) {
        int u = __shfl_up_sync(0xffffffffu, v, o);
        if (lane >= o) v += u;
    }
    if (lane == 31) wsum[w] = v;
    __syncthreads();
    if (t < 32) {
        int u = wsum[t];
        #pragma unroll
        for (int o = 1; o < 32; o <<= 1) {
            int x = __shfl_up_sync(0xffffffffu, u, o);
            if (t >= o) u += x;
        }
        wsum[t] = u;
    }
    __syncthreads();
    int p = v - s + (w ? wsum[w-1] : 0);
    if (m0) idx[b*SEQ + p++] = 2*t;
    if (m1) idx[b*SEQ + p]   = 2*t + 1;
    if (t == 1023) cnt[b] = wsum[31];
}

// ---- W chunk streamer: 128 rows x 64 fp16 cols of weight, K-chunk kc ----------
__device__ __forceinline__ void stream_wchunk(__half* dst, const __half* __restrict__ W,
                                              int kc, int tid) {
    #pragma unroll
    for (int j = 0; j < 4; j++) {
        int i = tid + j * 256;
        int n = i >> 3, seg = (i & 7) * 8;     // 8 halves = 16B
        CPA16(s2u(dst + n * WH + seg), &W[(size_t)n * D + kc * 64 + seg], 16);
    }
}

// -------- QKV GEMM (fp16, M=64 tiles, K=64 chunks): fused LN -------------------
__global__ __launch_bounds__(256, 4) void qkv_kernel(const float* __restrict__ X,
        const __half* __restrict__ W0, const __half* __restrict__ W1,
        const __half* __restrict__ W2,
        const float* __restrict__ lnw, const float* __restrict__ lnb,
        float* __restrict__ xn_out,
        __half* __restrict__ O0, __half* __restrict__ O1, __half* __restrict__ O2) {
    extern __shared__ __half smh[];
    __half* sA  = smh;                    // MT x AH
    __half* sW0 = smh + MT * AH;          // 128 x WH
    __half* sW1 = sW0 + 128 * WH;
    int tid = threadIdx.x, warp = tid >> 5, lane = tid & 31;
    int rq = warp >> 1, nh = warp & 1;
    int g = lane >> 2, tig = lane & 3;
    int rowBase = blockIdx.x * MT;

    const __half* Ws[3] = {W0, W1, W2};
    __half* Os[3] = {O0, O1, O2};

    stream_wchunk(sW0, W0, 0, tid);
    CPC();
    ln_gmem_f16(X, rowBase, tid, lnw, lnb, sA, xn_out);
    CPW0();
    __syncthreads();

    unsigned aBase = s2u(sA) +
        (((rq * 16 + (lane & 7) + ((lane >> 3) & 1) * 8) * AH + (lane >> 4) * 8) << 1);
    unsigned wOff = ((((lane & 7) + nh * 64) * WH + (lane >> 3) * 8) << 1);
    unsigned wBase[2] = { s2u(sW0) + wOff, s2u(sW1) + wOff };

    float c[8][4] = {};
    int buf = 0;

    #pragma unroll
    for (int t = 0; t < 6; t++) {
        int wi = t >> 1, kc = t & 1;
        if (t) __syncthreads();
        if (t + 1 < 6) {
            stream_wchunk(buf ? sW0 : sW1, Ws[(t + 1) >> 1], (t + 1) & 1, tid);
            CPC();
            CPW1();
        } else {
            CPW0();
        }
        __syncthreads();

        unsigned a[4][4];
        #pragma unroll
        for (int ks = 0; ks < 4; ks++)
            LDSM_X4(a[ks], aBase + kc * 128 + ks * 32);
        #pragma unroll
        for (int nt = 0; nt < 8; nt++) {
            unsigned wb0[4], wb1[4];
            LDSM_X4(wb0, wBase[buf] + nt * (8 * WH * 2));
            LDSM_X4(wb1, wBase[buf] + nt * (8 * WH * 2) + 64);
            MMA_F16(c[nt], a[0], wb0[0], wb0[1]);
            MMA_F16(c[nt], a[1], wb0[2], wb0[3]);
            MMA_F16(c[nt], a[2], wb1[0], wb1[1]);
            MMA_F16(c[nt], a[3], wb1[2], wb1[3]);
        }

        if (kc == 1) {
            __half* O = Os[wi];
            int row0 = rowBase + rq * 16 + g;
            bool relu = (wi == 0);
            #pragma unroll
            for (int nt = 0; nt < 8; nt++) {
                int col = nh * 64 + nt * 8 + 2 * tig;
                float lx = c[nt][0], ly = c[nt][1], hx = c[nt][2], hy = c[nt][3];
                if (relu) {
                    lx = fmaxf(lx, 0.f); ly = fmaxf(ly, 0.f);
                    hx = fmaxf(hx, 0.f); hy = fmaxf(hy, 0.f);
                }
                *(unsigned*)&O[(size_t)row0 * D + col]       = packh(lx, ly);
                *(unsigned*)&O[(size_t)(row0 + 8) * D + col] = packh(hx, hy);
                c[nt][0] = 0.f; c[nt][1] = 0.f; c[nt][2] = 0.f; c[nt][3] = 0.f;
            }
        }
        buf ^= 1;
    }
}

// -------- FFN (fp16, M=64, K=64 chunks): out = sa + relu(LN(sa)@w1+b1)@w2 + b2 -
__global__ __launch_bounds__(256, 4) void ffn_kernel(const float* __restrict__ SA,
        const __half* __restrict__ W1, const __half* __restrict__ W2,
        const float* __restrict__ lnw, const float* __restrict__ lnb,
        const float* __restrict__ b1v, const float* __restrict__ b2v,
        float* __restrict__ out) {
    extern __shared__ __half smh[];
    __half* sA  = smh;
    __half* sW0 = smh + MT * AH;
    __half* sW1 = sW0 + 128 * WH;
    int tid = threadIdx.x, warp = tid >> 5, lane = tid & 31;
    int rq = warp >> 1, nh = warp & 1;
    int g = lane >> 2, tig = lane & 3;
    int rowBase = blockIdx.x * MT;

    stream_wchunk(sW0, W1, 0, tid);
    CPC();
    ln_gmem_f16(SA, rowBase, tid, lnw, lnb, sA, nullptr);
    CPW0();
    __syncthreads();

    unsigned aBase = s2u(sA) +
        (((rq * 16 + (lane & 7) + ((lane >> 3) & 1) * 8) * AH + (lane >> 4) * 8) << 1);
    unsigned wOff = ((((lane & 7) + nh * 64) * WH + (lane >> 3) * 8) << 1);
    unsigned wBase[2] = { s2u(sW0) + wOff, s2u(sW1) + wOff };

    float c[8][4] = {};
    int buf = 0;

    #pragma unroll
    for (int t = 0; t < 4; t++) {
        int kc = t & 1;
        if (t) __syncthreads();
        if (t + 1 < 4) {
            stream_wchunk(buf ? sW0 : sW1, (t + 1 < 2) ? W1 : W2, (t + 1) & 1, tid);
            CPC();
            CPW1();
        } else {
            CPW0();
        }
        __syncthreads();

        unsigned a[4][4];
        #pragma unroll
        for (int ks = 0; ks < 4; ks++)
            LDSM_X4(a[ks], aBase + kc * 128 + ks * 32);
        #pragma unroll
        for (int nt = 0; nt < 8; nt++) {
            unsigned wb0[4], wb1[4];
            LDSM_X4(wb0, wBase[buf] + nt * (8 * WH * 2));
            LDSM_X4(wb1, wBase[buf] + nt * (8 * WH * 2) + 64);
            MMA_F16(c[nt], a[0], wb0[0], wb0[1]);
            MMA_F16(c[nt], a[1], wb0[2], wb0[3]);
            MMA_F16(c[nt], a[2], wb1[0], wb1[1]);
            MMA_F16(c[nt], a[3], wb1[2], wb1[3]);
        }

        if (t == 1) {
            // f1 = fp16(relu(c + b1)) overwrites consumed A tile
            __syncthreads();
            int row0l = rq * 16 + g;
            #pragma unroll
            for (int nt = 0; nt < 8; nt++) {
                int col = nh * 64 + nt * 8 + 2 * tig;
                float2 bb = *(const float2*)&b1v[col];
                *(unsigned*)&sA[row0l * AH + col] =
                    packh(fmaxf(c[nt][0] + bb.x, 0.f), fmaxf(c[nt][1] + bb.y, 0.f));
                *(unsigned*)&sA[(row0l + 8) * AH + col] =
                    packh(fmaxf(c[nt][2] + bb.x, 0.f), fmaxf(c[nt][3] + bb.y, 0.f));
                c[nt][0] = 0.f; c[nt][1] = 0.f; c[nt][2] = 0.f; c[nt][3] = 0.f;
            }
        }
        if (t == 3) {
            int row0 = rowBase + rq * 16 + g;
            #pragma unroll
            for (int nt = 0; nt < 8; nt++) {
                int col = nh * 64 + nt * 8 + 2 * tig;
                float2 bb = *(const float2*)&b2v[col];
                float2 r0v = *(const float2*)&SA[(size_t)row0 * D + col];
                float2 r1v = *(const float2*)&SA[(size_t)(row0 + 8) * D + col];
                float2 lo = make_float2(c[nt][0] + bb.x + r0v.x, c[nt][1] + bb.y + r0v.y);
                float2 hi = make_float2(c[nt][2] + bb.x + r1v.x, c[nt][3] + bb.y + r1v.y);
                *(float2*)&out[(size_t)row0 * D + col] = lo;
                *(float2*)&out[(size_t)(row0 + 8) * D + col] = hi;
            }
        }
        buf ^= 1;
    }
}

// ---------------- fp16 flash attention: reg-diet, 4 CTA/SM ---------------------
#define AKS 40
__global__ __launch_bounds__(256, 4) void attn_f16_kernel(
        const __half* __restrict__ gqh, const __half* __restrict__ gkh,
        const __half* __restrict__ gvh, const int* __restrict__ idx,
        const int* __restrict__ cnt, const float* __restrict__ xn,
        float* __restrict__ sa) {
    __shared__ __half sK[2][64][AKS];
    __shared__ __half sV[2][64][AKS];

    int tid = threadIdx.x;
    int warp = tid >> 5, lane = tid & 31;
    int g = lane >> 2, tig = lane & 3;
    int b = blockIdx.y >> 2, h = blockIdx.y & 3;
    int q0 = blockIdx.x * 128 + warp * 16;
    int nb = cnt[b];
    const int* bidx = idx + b * SEQ;

    unsigned onesb = (lane < 4) ? 0x3C003C00u : 0u;

    const float qs = 0.17677669529663687f * 1.4426950408889634f;
    const __half* qp0 = gqh + (size_t)(b * SEQ + q0 + g) * D + h * DK;
    const __half* qp1 = qp0 + 8 * D;
    unsigned qa[2][4];
    #pragma unroll
    for (int ks = 0; ks < 2; ks++) {
        int base = ks * 16 + 2 * tig;
        qa[ks][0] = packh(__half2float(qp0[base]) * qs,     __half2float(qp0[base + 1]) * qs);
        qa[ks][1] = packh(__half2float(qp1[base]) * qs,     __half2float(qp1[base + 1]) * qs);
        qa[ks][2] = packh(__half2float(qp0[base + 8]) * qs, __half2float(qp0[base + 9]) * qs);
        qa[ks][3] = packh(__half2float(qp1[base + 8]) * qs, __half2float(qp1[base + 9]) * qs);
    }

    float o[5][4] = {};          // [0..3]: O d-tiles; [4]: l tile (col 0)

    int fKey = tid >> 2, fSeg = (tid & 3) * 8;
    size_t headOff = (size_t)b * SEQ * D + h * DK + fSeg;

    int kRow = lane & 7, kCol = (lane >> 3) * 8;
    int vKey = ((lane >> 3) & 1) * 8 + (lane & 7);
    int vCol = (lane >> 4) * 8;
    unsigned vB[2] = { s2u(&sV[0][vKey][vCol]), s2u(&sV[1][vKey][vCol]) };

    {
        int p = (fKey < nb) ? 16 : 0;
        int gi = (fKey < nb) ? bidx[fKey] : 0;
        CPA16(s2u(&sK[0][fKey][fSeg]), gkh + headOff + (size_t)gi * D, p);
        CPA16(s2u(&sV[0][fKey][fSeg]), gvh + headOff + (size_t)gi * D, p);
        CPC();
    }

    int buf = 0;
    for (int kb = 0; kb < nb; kb += 64, buf ^= 1) {
        int kv = min(64, nb - kb);
        CPW0();
        __syncthreads();
        if (kb + 64 < nb) {
            int rem = nb - (kb + 64);
            int p = (fKey < rem) ? 16 : 0;
            int gi = (fKey < rem) ? bidx[kb + 64 + fKey] : 0;
            CPA16(s2u(&sK[buf ^ 1][fKey][fSeg]), gkh + headOff + (size_t)gi * D, p);
            CPA16(s2u(&sV[buf ^ 1][fKey][fSeg]), gvh + headOff + (size_t)gi * D, p);
            CPC();
        }

        unsigned kAddr = s2u(&sK[buf][kRow][kCol]);

        unsigned p01[8], p23[8];
        #pragma unroll
        for (int nt = 0; nt < 8; nt++) {
            float s4[4] = {0.f, 0.f, 0.f, 0.f};
            unsigned kf[4];
            LDSM_X4(kf, kAddr + nt * 8 * AKS * 2);
            MMA_F16(s4, qa[0], kf[0], kf[1]);
            MMA_F16(s4, qa[1], kf[2], kf[3]);
            if (kv < 64) {
                int col = nt * 8 + 2 * tig;
                if (col     >= kv) { s4[0] = -1000.f; s4[2] = -1000.f; }
                if (col + 1 >= kv) { s4[1] = -1000.f; s4[3] = -1000.f; }
            }
            p01[nt] = h2exp2(s4[0], s4[1]);
            p23[nt] = h2exp2(s4[2], s4[3]);
        }

        #pragma unroll
        for (int ksp = 0; ksp < 4; ksp++) {
            unsigned pa[4] = { p01[2*ksp], p23[2*ksp], p01[2*ksp+1], p23[2*ksp+1] };
            #pragma unroll
            for (int dh = 0; dh < 2; dh++) {
                unsigned vb[4];
                LDSM_X4_T(vb, vB[buf] + (ksp * 16 * AKS + dh * 16) * 2);
                MMA_F16(o[dh*2 + 0], pa, vb[0], vb[1]);
                MMA_F16(o[dh*2 + 1], pa, vb[2], vb[3]);
            }
            MMA_F16(o[4], pa, onesb, onesb);
        }
    }

    // epilogue: sa = xn + O/l
    float l0 = __shfl_sync(0xffffffffu, o[4][0], lane & 28);
    float l1 = __shfl_sync(0xffffffffu, o[4][2], lane & 28);
    float inv0 = (l0 > 0.f) ? 1.f / l0 : 0.f;
    float inv1 = (l1 > 0.f) ? 1.f / l1 : 0.f;
    const float* xp0 = xn + (size_t)(b * SEQ + q0 + g) * D + h * DK;
    const float* xp1 = xp0 + 8 * D;
    float* op0 = sa + (size_t)(b * SEQ + q0 + g) * D + h * DK;
    float* op1 = op0 + 8 * D;
    #pragma unroll
    for (int nt = 0; nt < 4; nt++) {
        int col = nt * 8 + 2 * tig;
        float2 x0 = *(const float2*)(xp0 + col);
        float2 x1 = *(const float2*)(xp1 + col);
        *(float2*)(op0 + col) = make_float2(o[nt][0] * inv0 + x0.x, o[nt][1] * inv0 + x0.y);
        *(float2*)(op1 + col) = make_float2(o[nt][2] * inv1 + x1.x, o[nt][3] * inv1 + x1.y);
    }
}

// ---------------- launch ---------------------------------------------------------
extern "C" void kernel_launch(void* const* d_in, const int* in_sizes, int n_in,
                              void* d_out, int out_size) {
    const float* x    = (const float*)d_in[0];
    const int*   mask = (const int*)  d_in[1];
    const float* ln_w = (const float*)d_in[2];
    const float* ln_b = (const float*)d_in[3];
    const float* wq   = (const float*)d_in[4];
    const float* wk   = (const float*)d_in[5];
    const float* wv   = (const float*)d_in[6];
    const float* w1   = (const float*)d_in[7];
    const float* b1   = (const float*)d_in[8];
    const float* w2   = (const float*)d_in[9];
    const float* b2   = (const float*)d_in[10];
    float* out = (float*)d_out;

    float *xn, *sa;
    int *cntp, *idxp;
    __half *wh, *qh, *kh, *vh;
    cudaGetSymbolAddress((void**)&xn,   g_xn);
    cudaGetSymbolAddress((void**)&sa,   g_sa);
    cudaGetSymbolAddress((void**)&wh,   g_wh);
    cudaGetSymbolAddress((void**)&cntp, g_cnt);
    cudaGetSymbolAddress((void**)&idxp, g_idx);
    cudaGetSymbolAddress((void**)&qh,   g_qh);
    cudaGetSymbolAddress((void**)&kh,   g_kh);
    cudaGetSymbolAddress((void**)&vh,   g_vh);

    cudaFuncSetAttribute(qkv_kernel, cudaFuncAttributeMaxDynamicSharedMemorySize, GEMM_SMEM);
    cudaFuncSetAttribute(ffn_kernel, cudaFuncAttributeMaxDynamicSharedMemorySize, GEMM_SMEM);

    // 0) compact key indices + fp16-convert weights
    prep_kernel<<<96, 1024>>>(mask, idxp, cntp, wq, wk, wv, w1, w2, wh);
    // 1) fused LN + QKV (fp16, M=64, K=64 chunks)
    qkv_kernel<<<ROWS/MT, 256, GEMM_SMEM>>>(x, wh, wh + 16384, wh + 32768,
            ln_w, ln_b, xn, qh, kh, vh);
    // 2) attention (writes sa = xn + attn)
    attn_f16_kernel<<<dim3(SEQ/128, BATCH*H), 256>>>(qh, kh, vh, idxp, cntp, xn, sa);
    // 3) fused LN + FFN (fp16, M=64, K=64 chunks)
    ffn_kernel<<<ROWS/MT, 256, GEMM_SMEM>>>(sa, wh + 49152, wh + 65536,
            ln_w, ln_b, b1, b2, out);
}